// round 8
// baseline (speedup 1.0000x reference)
#include <cuda_runtime.h>
#include <cuda_bf16.h>
#include <cstdint>

#define S_LEN   2048
#define DMODEL  2048
#define DKV     512
#define NH      32
#define NKV     8
#define HD      64

// ---------------- scratch (static device globals; no allocation) ----------------
__device__ __align__(16) int8_t g_q8[S_LEN * DMODEL];   // 4 MB
__device__ float  g_qs[S_LEN * NH];
__device__ __align__(16) int8_t g_k8[S_LEN * DKV];      // 1 MB
__device__ float  g_ks[S_LEN * NKV];
__device__ __align__(16) float  g_v [S_LEN * DKV];      // 4 MB

// bf16 hi/lo split buffers
__device__ __align__(16) __nv_bfloat16 g_xh[S_LEN * DMODEL],   g_xl[S_LEN * DMODEL];
__device__ __align__(16) __nv_bfloat16 g_wh[3072 * DMODEL],    g_wl[3072 * DMODEL];
__device__ __align__(16) __nv_bfloat16 g_woh[DMODEL * DMODEL], g_wol[DMODEL * DMODEL];
__device__ __align__(16) __nv_bfloat16 g_ah[S_LEN * DMODEL],   g_al[S_LEN * DMODEL];

#define NEG_INF (__int_as_float(0xff800000))

// =====================================================================
// helpers
// =====================================================================
__device__ __forceinline__ void mma_bf16(float* c, const uint32_t* a,
                                         uint32_t b0, uint32_t b1) {
    asm volatile(
        "mma.sync.aligned.m16n8k16.row.col.f32.bf16.bf16.f32 "
        "{%0,%1,%2,%3}, {%4,%5,%6,%7}, {%8,%9}, {%0,%1,%2,%3};"
        : "+f"(c[0]), "+f"(c[1]), "+f"(c[2]), "+f"(c[3])
        : "r"(a[0]), "r"(a[1]), "r"(a[2]), "r"(a[3]), "r"(b0), "r"(b1));
}

__device__ __forceinline__ void mma_s8(int* c, const int* a, int b0, int b1) {
    asm volatile(
        "mma.sync.aligned.m16n8k32.row.col.s32.s8.s8.s32 "
        "{%0,%1,%2,%3}, {%4,%5,%6,%7}, {%8,%9}, {%0,%1,%2,%3};"
        : "+r"(c[0]), "+r"(c[1]), "+r"(c[2]), "+r"(c[3])
        : "r"(a[0]), "r"(a[1]), "r"(a[2]), "r"(a[3]), "r"(b0), "r"(b1));
}

__device__ __forceinline__ void mma_tf32(float* c, unsigned a0, unsigned a1,
                                         unsigned a2, unsigned a3,
                                         unsigned b0, unsigned b1) {
    asm volatile(
        "mma.sync.aligned.m16n8k8.row.col.f32.tf32.tf32.f32 "
        "{%0,%1,%2,%3}, {%4,%5,%6,%7}, {%8,%9}, {%0,%1,%2,%3};"
        : "+f"(c[0]), "+f"(c[1]), "+f"(c[2]), "+f"(c[3])
        : "r"(a0), "r"(a1), "r"(a2), "r"(a3), "r"(b0), "r"(b1));
}

__device__ __forceinline__ float tf32r(float x) {
    unsigned u;
    asm("cvt.rna.tf32.f32 %0, %1;" : "=r"(u) : "f"(x));
    return __uint_as_float(u);
}

#define LDSM4(r, a) \
    asm volatile("ldmatrix.sync.aligned.m8n8.x4.shared.b16 {%0,%1,%2,%3}, [%4];" \
                 : "=r"((r)[0]), "=r"((r)[1]), "=r"((r)[2]), "=r"((r)[3]) : "r"(a))

#define CP_ASYNC16(dst, src) \
    asm volatile("cp.async.ca.shared.global [%0], [%1], 16;" :: "r"(dst), "l"(src))
#define CP_COMMIT() asm volatile("cp.async.commit_group;")
#define CP_WAIT(n)  asm volatile("cp.async.wait_group %0;" :: "n"(n))

__device__ __forceinline__ uint32_t smem_u32(const void* p) {
    uint32_t a;
    asm("{ .reg .u64 t; cvta.to.shared.u64 t, %1; cvt.u32.u64 %0, t; }" : "=r"(a) : "l"(p));
    return a;
}

// =====================================================================
// Prep: split fp32 inputs into bf16 hi/lo pairs (memory-bound)
// =====================================================================
__device__ __forceinline__ void split4(float4 v, __nv_bfloat16* dh, __nv_bfloat16* dl, size_t e) {
    __nv_bfloat16 h0 = __float2bfloat16(v.x), h1 = __float2bfloat16(v.y);
    __nv_bfloat16 h2 = __float2bfloat16(v.z), h3 = __float2bfloat16(v.w);
    __nv_bfloat162 a, b;
    a.x = h0; a.y = h1; b.x = h2; b.y = h3;
    *reinterpret_cast<__nv_bfloat162*>(dh + e)     = a;
    *reinterpret_cast<__nv_bfloat162*>(dh + e + 2) = b;
    __nv_bfloat162 c, d;
    c.x = __float2bfloat16(v.x - __bfloat162float(h0));
    c.y = __float2bfloat16(v.y - __bfloat162float(h1));
    d.x = __float2bfloat16(v.z - __bfloat162float(h2));
    d.y = __float2bfloat16(v.w - __bfloat162float(h3));
    *reinterpret_cast<__nv_bfloat162*>(dl + e)     = c;
    *reinterpret_cast<__nv_bfloat162*>(dl + e + 2) = d;
}

__global__ __launch_bounds__(256) void prep_kernel(
    const float* __restrict__ x, const float* __restrict__ Wq,
    const float* __restrict__ Wk, const float* __restrict__ Wv,
    const float* __restrict__ Wo)
{
    const int NX = S_LEN * DMODEL / 4;
    const int NW = 3072 * DMODEL / 4;
    const int NO = DMODEL * DMODEL / 4;
    const int total = NX + NW + NO;
    for (int i = blockIdx.x * blockDim.x + threadIdx.x; i < total;
         i += gridDim.x * blockDim.x) {
        if (i < NX) {
            float4 v = reinterpret_cast<const float4*>(x)[i];
            split4(v, g_xh, g_xl, (size_t)i * 4);
        } else if (i < NX + NW) {
            int j = i - NX;
            int row = j >> 9;
            int c4  = j & 511;
            float4 v;
            if (row < 2048)      v = reinterpret_cast<const float4*>(Wq)[row * 512 + c4];
            else if (row < 2560) v = reinterpret_cast<const float4*>(Wk)[(row - 2048) * 512 + c4];
            else                 v = reinterpret_cast<const float4*>(Wv)[(row - 2560) * 512 + c4];
            split4(v, g_wh, g_wl, (size_t)j * 4);
        } else {
            int j = i - NX - NW;
            float4 v = reinterpret_cast<const float4*>(Wo)[j];
            split4(v, g_woh, g_wol, (size_t)j * 4);
        }
    }
}

// =====================================================================
// Tensor-core GEMM v4: CTA 128x256, 8 warps of 64x64, BK=16,
//   4-stage cp.async pipeline, one sync per K-iter, 1 CTA/SM.
//   Stage: Ah(128x48B) Al Bh(256x48B) Bl = 36864B
// =====================================================================
#define GP       48
#define A_TILE   6144          // 128 * 48
#define B_TILE   12288         // 256 * 48
#define STAGE_B  36864
#define NSTAGE   4
#define SMEM_DYN (NSTAGE * STAGE_B)   // 147456
#define KITER    128

__global__ __launch_bounds__(256, 1) void tc_gemm(float* __restrict__ outp, int flavor)
{
    extern __shared__ char smem[];
    const uint32_t sbase = smem_u32(smem);
    const int tid  = threadIdx.x;
    const int wid  = tid >> 5;
    const int lane = tid & 31;
    const int m0   = blockIdx.y * 128;
    const int n0   = blockIdx.x * 256;
    const int wm   = (wid & 1) * 64;
    const int wn   = (wid >> 1) * 64;

    const __nv_bfloat16 *aH, *aL, *bH, *bL;
    int mode;                                  // 0=Qquant 1=Kquant 2=V 3=out
    int nb;                                    // B-local row base for this CTA
    if (flavor == 1) { aH = g_ah; aL = g_al; bH = g_woh; bL = g_wol; mode = 3; nb = n0; }
    else {
        aH = g_xh; aL = g_xl; bH = g_wh; bL = g_wl;
        mode = (n0 < 2048) ? 0 : (n0 < 2560) ? 1 : 2;
        nb = n0;                               // g_wh holds all 3072 rows contiguously
    }
    const __nv_bfloat16* srcs[4] = {
        aH + (size_t)m0 * DMODEL, aL + (size_t)m0 * DMODEL,
        bH + (size_t)nb * DMODEL, bL + (size_t)nb * DMODEL };

    // cp.async: thread t covers row r=t>>1, 16B chunk s=t&1 in 6 tiles-rows
    const int r0  = tid >> 1;
    const int sb  = (tid & 1) * 16;            // byte offset in row
    const size_t go = (size_t)r0 * DMODEL + (tid & 1) * 8;

    // ldmatrix base addresses (within a stage)
    const uint32_t aAddr = sbase + (wm + (lane & 15)) * GP + ((lane >> 4) << 4);
    const uint32_t bAddr = sbase + 2 * A_TILE +
        (wn + (lane & 7) + ((lane >> 4) & 1) * 8) * GP + (((lane >> 3) & 1) << 4);

    float acc[4][8][4];
#pragma unroll
    for (int mt = 0; mt < 4; mt++)
#pragma unroll
        for (int nt = 0; nt < 8; nt++)
#pragma unroll
            for (int i = 0; i < 4; i++) acc[mt][nt][i] = 0.f;

    auto load_stage = [&](int it) {
        const int kc = it * 16;
        const uint32_t db = sbase + (it & (NSTAGE - 1)) * STAGE_B + r0 * GP + sb;
        CP_ASYNC16(db,                       (const char*)(srcs[0] + go + kc));
        CP_ASYNC16(db + A_TILE,              (const char*)(srcs[1] + go + kc));
        CP_ASYNC16(db + 2 * A_TILE,          (const char*)(srcs[2] + go + kc));
        CP_ASYNC16(db + 2 * A_TILE + 128 * GP,
                   (const char*)(srcs[2] + go + (size_t)128 * DMODEL + kc));
        CP_ASYNC16(db + 2 * A_TILE + B_TILE, (const char*)(srcs[3] + go + kc));
        CP_ASYNC16(db + 2 * A_TILE + B_TILE + 128 * GP,
                   (const char*)(srcs[3] + go + (size_t)128 * DMODEL + kc));
    };

    load_stage(0); CP_COMMIT();
    load_stage(1); CP_COMMIT();
    load_stage(2); CP_COMMIT();

    for (int it = 0; it < KITER; it++) {
        CP_WAIT(2);
        __syncthreads();
        if (it + 3 < KITER) load_stage(it + 3);
        CP_COMMIT();

        const uint32_t off = (it & (NSTAGE - 1)) * STAGE_B;
        const uint32_t ab = aAddr + off;
        const uint32_t bb = bAddr + off;
        uint32_t ah[4][4], al[4][4], bh[4][4], bl[4][4];
#pragma unroll
        for (int q = 0; q < 4; q++) {
            LDSM4(ah[q], ab + q * (16 * GP));
            LDSM4(al[q], ab + q * (16 * GP) + A_TILE);
        }
#pragma unroll
        for (int np = 0; np < 4; np++) {
            LDSM4(bh[np], bb + np * (16 * GP));
            LDSM4(bl[np], bb + np * (16 * GP) + B_TILE);
        }
#pragma unroll
        for (int mt = 0; mt < 4; mt++)
#pragma unroll
            for (int nt = 0; nt < 8; nt++) {
                uint32_t h0 = bh[nt >> 1][(nt & 1) * 2];
                uint32_t h1 = bh[nt >> 1][(nt & 1) * 2 + 1];
                uint32_t l0 = bl[nt >> 1][(nt & 1) * 2];
                uint32_t l1 = bl[nt >> 1][(nt & 1) * 2 + 1];
                mma_bf16(acc[mt][nt], ah[mt], h0, h1);
                mma_bf16(acc[mt][nt], ah[mt], l0, l1);
                mma_bf16(acc[mt][nt], al[mt], h0, h1);
            }
    }

    // ---- epilogue: each warp covers 64 rows x 64 cols (= one head in N) ----
    const int qrow = lane >> 2;
    const int qcol = (lane & 3) * 2;
    const int ncol = n0 + wn;                  // global col base of this warp
#pragma unroll
    for (int mt = 0; mt < 4; mt++) {
#pragma unroll
        for (int h = 0; h < 2; h++) {
            const int row = m0 + wm + mt * 16 + qrow + h * 8;
            if (mode <= 1) {
                float am = 0.f;
#pragma unroll
                for (int nt = 0; nt < 8; nt++)
                    am = fmaxf(am, fmaxf(fabsf(acc[mt][nt][h * 2]),
                                         fabsf(acc[mt][nt][h * 2 + 1])));
                am = fmaxf(am, __shfl_xor_sync(0xffffffffu, am, 1));
                am = fmaxf(am, __shfl_xor_sync(0xffffffffu, am, 2));
                float scale = 127.f / fmaxf(am, 1e-6f);
#pragma unroll
                for (int nt = 0; nt < 8; nt++) {
                    int v0 = min(127, max(-127, __float2int_rn(acc[mt][nt][h * 2]     * scale)));
                    int v1 = min(127, max(-127, __float2int_rn(acc[mt][nt][h * 2 + 1] * scale)));
                    unsigned short pk = (unsigned short)((v0 & 255) | ((v1 & 255) << 8));
                    if (mode == 0)
                        *reinterpret_cast<unsigned short*>(
                            &g_q8[(size_t)row * DMODEL + ncol + nt * 8 + qcol]) = pk;
                    else
                        *reinterpret_cast<unsigned short*>(
                            &g_k8[(size_t)row * DKV + (ncol - 2048) + nt * 8 + qcol]) = pk;
                }
                if ((lane & 3) == 0) {
                    if (mode == 0) g_qs[row * NH  + (ncol >> 6)]          = scale;
                    else           g_ks[row * NKV + ((ncol - 2048) >> 6)] = scale;
                }
            } else {
#pragma unroll
                for (int nt = 0; nt < 8; nt++) {
                    float2 v = make_float2(acc[mt][nt][h * 2], acc[mt][nt][h * 2 + 1]);
                    if (mode == 2)
                        *reinterpret_cast<float2*>(
                            &g_v[(size_t)row * DKV + (ncol - 2560) + nt * 8 + qcol]) = v;
                    else
                        *reinterpret_cast<float2*>(
                            &outp[(size_t)row * DMODEL + ncol + nt * 8 + qcol]) = v;
                }
            }
        }
    }
}

// =====================================================================
// Attention kernel (round-2 design; epilogue writes bf16 hi/lo)
// =====================================================================
__global__ __launch_bounds__(128) void attn_kernel()
{
    const int h    = blockIdx.y;
    const int qb   = gridDim.x - 1 - blockIdx.x;
    const int kvh  = h >> 2;
    const int tid  = threadIdx.x;
    const int warp = tid >> 5;
    const int lane = tid & 31;
    const int g    = lane >> 2;
    const int tg   = lane & 3;
    const int rbase = warp * 16;

    __shared__ int   qsm[64][20];
    __shared__ int   ksm[64][20];
    __shared__ float vsm[64][72];
    __shared__ float psm[64][68];
    __shared__ float qfac[64];
    __shared__ float kinv[64];

#pragma unroll
    for (int i = 0; i < 2; i++) {
        int idx = tid + i * 128;
        int row = idx >> 2;
        int seg = idx & 3;
        int4 v = *reinterpret_cast<const int4*>(
            &g_q8[(size_t)(qb * 64 + row) * DMODEL + h * 64 + seg * 16]);
        *reinterpret_cast<int4*>(&qsm[row][seg * 4]) = v;
    }
    if (tid < 64) qfac[tid] = 0.125f / g_qs[(qb * 64 + tid) * NH + h];
    __syncthreads();

    int qa[2][4];
#pragma unroll
    for (int s = 0; s < 2; s++) {
        qa[s][0] = qsm[rbase + g    ][s * 8 + tg];
        qa[s][1] = qsm[rbase + g + 8][s * 8 + tg];
        qa[s][2] = qsm[rbase + g    ][s * 8 + 4 + tg];
        qa[s][3] = qsm[rbase + g + 8][s * 8 + 4 + tg];
    }

    const int   rowA = rbase + g, rowB = rowA + 8;
    const float qfA  = qfac[rowA], qfB = qfac[rowB];
    const int   qgA  = qb * 64 + rowA, qgB = qb * 64 + rowB;

    float acc[8][4];
#pragma unroll
    for (int nt = 0; nt < 8; nt++)
#pragma unroll
        for (int i = 0; i < 4; i++) acc[nt][i] = 0.f;
    float m_runA = NEG_INF, m_runB = NEG_INF;
    float l_runA = 0.f,     l_runB = 0.f;

    for (int j = 0; j <= qb; j++) {
#pragma unroll
        for (int i = 0; i < 2; i++) {
            int idx = tid + i * 128;
            int row = idx >> 2;
            int seg = idx & 3;
            int4 v = *reinterpret_cast<const int4*>(
                &g_k8[(size_t)(j * 64 + row) * DKV + kvh * 64 + seg * 16]);
            *reinterpret_cast<int4*>(&ksm[row][seg * 4]) = v;
        }
        if (tid < 64) kinv[tid] = 1.f / g_ks[(j * 64 + tid) * NKV + kvh];
#pragma unroll
        for (int i = 0; i < 8; i++) {
            int idx = tid + i * 128;
            int row = idx >> 4;
            int c4  = (idx & 15) << 2;
            float4 vv = *reinterpret_cast<const float4*>(
                &g_v[(size_t)(j * 64 + row) * DKV + kvh * 64 + c4]);
            vv.x = tf32r(vv.x); vv.y = tf32r(vv.y);
            vv.z = tf32r(vv.z); vv.w = tf32r(vv.w);
            *reinterpret_cast<float4*>(&vsm[row][c4]) = vv;
        }
        __syncthreads();

        int sc[8][4];
#pragma unroll
        for (int nt = 0; nt < 8; nt++) {
            sc[nt][0] = sc[nt][1] = sc[nt][2] = sc[nt][3] = 0;
#pragma unroll
            for (int s = 0; s < 2; s++) {
                int b0 = ksm[nt * 8 + g][s * 8 + tg];
                int b1 = ksm[nt * 8 + g][s * 8 + 4 + tg];
                mma_s8(sc[nt], qa[s], b0, b1);
            }
        }

        const bool maskblk = (j == qb);
        float sv[8][4];
        float mxA = NEG_INF, mxB = NEG_INF;
#pragma unroll
        for (int nt = 0; nt < 8; nt++) {
            int colbase = nt * 8 + tg * 2;
            float2 kv = *reinterpret_cast<const float2*>(&kinv[colbase]);
            float s0 = (float)sc[nt][0] * qfA * kv.x;
            float s1 = (float)sc[nt][1] * qfA * kv.y;
            float s2 = (float)sc[nt][2] * qfB * kv.x;
            float s3 = (float)sc[nt][3] * qfB * kv.y;
            if (maskblk) {
                int col = j * 64 + colbase;
                if (col     > qgA) s0 = NEG_INF;
                if (col + 1 > qgA) s1 = NEG_INF;
                if (col     > qgB) s2 = NEG_INF;
                if (col + 1 > qgB) s3 = NEG_INF;
            }
            sv[nt][0] = s0; sv[nt][1] = s1; sv[nt][2] = s2; sv[nt][3] = s3;
            mxA = fmaxf(mxA, fmaxf(s0, s1));
            mxB = fmaxf(mxB, fmaxf(s2, s3));
        }
        mxA = fmaxf(mxA, __shfl_xor_sync(0xffffffffu, mxA, 1));
        mxA = fmaxf(mxA, __shfl_xor_sync(0xffffffffu, mxA, 2));
        mxB = fmaxf(mxB, __shfl_xor_sync(0xffffffffu, mxB, 1));
        mxB = fmaxf(mxB, __shfl_xor_sync(0xffffffffu, mxB, 2));

        float mA = fmaxf(m_runA, mxA);
        float mB = fmaxf(m_runB, mxB);
        float aA = __expf(m_runA - mA);
        float aB = __expf(m_runB - mB);
        m_runA = mA; m_runB = mB;

        float sumA = 0.f, sumB = 0.f;
#pragma unroll
        for (int nt = 0; nt < 8; nt++) {
            int colbase = nt * 8 + tg * 2;
            float p0 = __expf(sv[nt][0] - mA);
            float p1 = __expf(sv[nt][1] - mA);
            float p2 = __expf(sv[nt][2] - mB);
            float p3 = __expf(sv[nt][3] - mB);
            sumA += p0 + p1; sumB += p2 + p3;
            float2 w0 = make_float2(tf32r(p0), tf32r(p1));
            float2 w1 = make_float2(tf32r(p2), tf32r(p3));
            *reinterpret_cast<float2*>(&psm[rowA][colbase]) = w0;
            *reinterpret_cast<float2*>(&psm[rowB][colbase]) = w1;
        }
        sumA += __shfl_xor_sync(0xffffffffu, sumA, 1);
        sumA += __shfl_xor_sync(0xffffffffu, sumA, 2);
        sumB += __shfl_xor_sync(0xffffffffu, sumB, 1);
        sumB += __shfl_xor_sync(0xffffffffu, sumB, 2);
        l_runA = l_runA * aA + sumA;
        l_runB = l_runB * aB + sumB;

#pragma unroll
        for (int nt = 0; nt < 8; nt++) {
            acc[nt][0] *= aA; acc[nt][1] *= aA;
            acc[nt][2] *= aB; acc[nt][3] *= aB;
        }

        __syncwarp();

#pragma unroll
        for (int ks = 0; ks < 8; ks++) {
            unsigned pa0 = __float_as_uint(psm[rowA][ks * 8 + tg]);
            unsigned pa1 = __float_as_uint(psm[rowB][ks * 8 + tg]);
            unsigned pa2 = __float_as_uint(psm[rowA][ks * 8 + 4 + tg]);
            unsigned pa3 = __float_as_uint(psm[rowB][ks * 8 + 4 + tg]);
#pragma unroll
            for (int nt = 0; nt < 8; nt++) {
                unsigned b0 = __float_as_uint(vsm[ks * 8 + tg    ][nt * 8 + g]);
                unsigned b1 = __float_as_uint(vsm[ks * 8 + tg + 4][nt * 8 + g]);
                mma_tf32(acc[nt], pa0, pa1, pa2, pa3, b0, b1);
            }
        }

        __syncthreads();
    }

    // ---- epilogue: write bf16 hi/lo for the tensor-core out-projection ----
    float ilA = 1.f / l_runA, ilB = 1.f / l_runB;
#pragma unroll
    for (int nt = 0; nt < 8; nt++) {
        int colbase = nt * 8 + tg * 2;
        float oA0 = acc[nt][0] * ilA, oA1 = acc[nt][1] * ilA;
        float oB0 = acc[nt][2] * ilB, oB1 = acc[nt][3] * ilB;
        size_t pA = (size_t)qgA * DMODEL + h * 64 + colbase;
        size_t pB = (size_t)qgB * DMODEL + h * 64 + colbase;
        __nv_bfloat162 hA, hB, lA, lB;
        hA.x = __float2bfloat16(oA0); hA.y = __float2bfloat16(oA1);
        hB.x = __float2bfloat16(oB0); hB.y = __float2bfloat16(oB1);
        lA.x = __float2bfloat16(oA0 - __bfloat162float(hA.x));
        lA.y = __float2bfloat16(oA1 - __bfloat162float(hA.y));
        lB.x = __float2bfloat16(oB0 - __bfloat162float(hB.x));
        lB.y = __float2bfloat16(oB1 - __bfloat162float(hB.y));
        *reinterpret_cast<__nv_bfloat162*>(&g_ah[pA]) = hA;
        *reinterpret_cast<__nv_bfloat162*>(&g_al[pA]) = lA;
        *reinterpret_cast<__nv_bfloat162*>(&g_ah[pB]) = hB;
        *reinterpret_cast<__nv_bfloat162*>(&g_al[pB]) = lB;
    }
}

// =====================================================================
extern "C" void kernel_launch(void* const* d_in, const int* in_sizes, int n_in,
                              void* d_out, int out_size)
{
    const float* x  = (const float*)d_in[0];
    const float* Wq = (const float*)d_in[1];
    const float* Wk = (const float*)d_in[2];
    const float* Wv = (const float*)d_in[3];
    const float* Wo = (const float*)d_in[4];
    float* out = (float*)d_out;

    cudaFuncSetAttribute(tc_gemm, cudaFuncAttributeMaxDynamicSharedMemorySize, SMEM_DYN);

    prep_kernel<<<592, 256>>>(x, Wq, Wk, Wv, Wo);
    tc_gemm<<<dim3(12, 16), 256, SMEM_DYN>>>(nullptr, 0);   // QKV + quant
    attn_kernel<<<dim3(32, 32), 128>>>();
    tc_gemm<<<dim3(8, 16), 256, SMEM_DYN>>>(out, 1);        // output projection
}

// round 9
// speedup vs baseline: 1.0628x; 1.0628x over previous
#include <cuda_runtime.h>
#include <cuda_bf16.h>
#include <cstdint>

#define S_LEN   2048
#define DMODEL  2048
#define DKV     512
#define NH      32
#define NKV     8
#define HD      64

// ---------------- scratch (static device globals; no allocation) ----------------
__device__ __align__(16) int8_t g_q8[S_LEN * DMODEL];   // 4 MB
__device__ float  g_qs[S_LEN * NH];
__device__ __align__(16) int8_t g_k8[S_LEN * DKV];      // 1 MB
__device__ float  g_ks[S_LEN * NKV];
__device__ __align__(16) float  g_v [S_LEN * DKV];      // 4 MB

// bf16 hi/lo split buffers
__device__ __align__(16) __nv_bfloat16 g_xh[S_LEN * DMODEL],   g_xl[S_LEN * DMODEL];
__device__ __align__(16) __nv_bfloat16 g_wh[3072 * DMODEL],    g_wl[3072 * DMODEL];
__device__ __align__(16) __nv_bfloat16 g_woh[DMODEL * DMODEL], g_wol[DMODEL * DMODEL];
__device__ __align__(16) __nv_bfloat16 g_ah[S_LEN * DMODEL],   g_al[S_LEN * DMODEL];

#define NEG_INF (__int_as_float(0xff800000))

// =====================================================================
// helpers
// =====================================================================
// NOTE: not volatile — register-only op, constraints carry all deps;
// lets ptxas interleave independent MMAs to hide HMMA latency.
__device__ __forceinline__ void mma_bf16(float* c, const uint32_t* a,
                                         uint32_t b0, uint32_t b1) {
    asm("mma.sync.aligned.m16n8k16.row.col.f32.bf16.bf16.f32 "
        "{%0,%1,%2,%3}, {%4,%5,%6,%7}, {%8,%9}, {%0,%1,%2,%3};"
        : "+f"(c[0]), "+f"(c[1]), "+f"(c[2]), "+f"(c[3])
        : "r"(a[0]), "r"(a[1]), "r"(a[2]), "r"(a[3]), "r"(b0), "r"(b1));
}

__device__ __forceinline__ void mma_s8(int* c, const int* a, int b0, int b1) {
    asm("mma.sync.aligned.m16n8k32.row.col.s32.s8.s8.s32 "
        "{%0,%1,%2,%3}, {%4,%5,%6,%7}, {%8,%9}, {%0,%1,%2,%3};"
        : "+r"(c[0]), "+r"(c[1]), "+r"(c[2]), "+r"(c[3])
        : "r"(a[0]), "r"(a[1]), "r"(a[2]), "r"(a[3]), "r"(b0), "r"(b1));
}

__device__ __forceinline__ void mma_tf32(float* c, unsigned a0, unsigned a1,
                                         unsigned a2, unsigned a3,
                                         unsigned b0, unsigned b1) {
    asm("mma.sync.aligned.m16n8k8.row.col.f32.tf32.tf32.f32 "
        "{%0,%1,%2,%3}, {%4,%5,%6,%7}, {%8,%9}, {%0,%1,%2,%3};"
        : "+f"(c[0]), "+f"(c[1]), "+f"(c[2]), "+f"(c[3])
        : "r"(a0), "r"(a1), "r"(a2), "r"(a3), "r"(b0), "r"(b1));
}

__device__ __forceinline__ float tf32r(float x) {
    unsigned u;
    asm("cvt.rna.tf32.f32 %0, %1;" : "=r"(u) : "f"(x));
    return __uint_as_float(u);
}

#define LDSM4(r, a) \
    asm volatile("ldmatrix.sync.aligned.m8n8.x4.shared.b16 {%0,%1,%2,%3}, [%4];" \
                 : "=r"((r)[0]), "=r"((r)[1]), "=r"((r)[2]), "=r"((r)[3]) : "r"(a))

#define CP_ASYNC16(dst, src) \
    asm volatile("cp.async.ca.shared.global [%0], [%1], 16;" :: "r"(dst), "l"(src))
#define CP_COMMIT() asm volatile("cp.async.commit_group;")
#define CP_WAIT(n)  asm volatile("cp.async.wait_group %0;" :: "n"(n))

__device__ __forceinline__ uint32_t smem_u32(const void* p) {
    uint32_t a;
    asm("{ .reg .u64 t; cvta.to.shared.u64 t, %1; cvt.u32.u64 %0, t; }" : "=r"(a) : "l"(p));
    return a;
}

// =====================================================================
// Prep: split fp32 inputs into bf16 hi/lo pairs (memory-bound)
// =====================================================================
__device__ __forceinline__ void split4(float4 v, __nv_bfloat16* dh, __nv_bfloat16* dl, size_t e) {
    __nv_bfloat16 h0 = __float2bfloat16(v.x), h1 = __float2bfloat16(v.y);
    __nv_bfloat16 h2 = __float2bfloat16(v.z), h3 = __float2bfloat16(v.w);
    __nv_bfloat162 a, b;
    a.x = h0; a.y = h1; b.x = h2; b.y = h3;
    *reinterpret_cast<__nv_bfloat162*>(dh + e)     = a;
    *reinterpret_cast<__nv_bfloat162*>(dh + e + 2) = b;
    __nv_bfloat162 c, d;
    c.x = __float2bfloat16(v.x - __bfloat162float(h0));
    c.y = __float2bfloat16(v.y - __bfloat162float(h1));
    d.x = __float2bfloat16(v.z - __bfloat162float(h2));
    d.y = __float2bfloat16(v.w - __bfloat162float(h3));
    *reinterpret_cast<__nv_bfloat162*>(dl + e)     = c;
    *reinterpret_cast<__nv_bfloat162*>(dl + e + 2) = d;
}

__global__ __launch_bounds__(256) void prep_kernel(
    const float* __restrict__ x, const float* __restrict__ Wq,
    const float* __restrict__ Wk, const float* __restrict__ Wv,
    const float* __restrict__ Wo)
{
    const int NX = S_LEN * DMODEL / 4;
    const int NW = 3072 * DMODEL / 4;
    const int NO = DMODEL * DMODEL / 4;
    const int total = NX + NW + NO;
    for (int i = blockIdx.x * blockDim.x + threadIdx.x; i < total;
         i += gridDim.x * blockDim.x) {
        if (i < NX) {
            float4 v = reinterpret_cast<const float4*>(x)[i];
            split4(v, g_xh, g_xl, (size_t)i * 4);
        } else if (i < NX + NW) {
            int j = i - NX;
            int row = j >> 9;
            int c4  = j & 511;
            float4 v;
            if (row < 2048)      v = reinterpret_cast<const float4*>(Wq)[row * 512 + c4];
            else if (row < 2560) v = reinterpret_cast<const float4*>(Wk)[(row - 2048) * 512 + c4];
            else                 v = reinterpret_cast<const float4*>(Wv)[(row - 2560) * 512 + c4];
            split4(v, g_wh, g_wl, (size_t)j * 4);
        } else {
            int j = i - NX - NW;
            float4 v = reinterpret_cast<const float4*>(Wo)[j];
            split4(v, g_woh, g_wol, (size_t)j * 4);
        }
    }
}

// =====================================================================
// Tensor-core GEMM v5: 4-stage cp.async pipeline, one sync per K-iter,
//   128x128 CTA tile, 8 warps of 32x64, BK=16, 2 CTA/SM.
//   TERM-MAJOR MMA ORDER: consecutive MMAs hit different accumulators.
// =====================================================================
#define GP       48
#define TILE_B   6144          // 128 * 48
#define STAGE_B  24576         // 4 tiles
#define NSTAGE   4
#define SMEM_DYN (NSTAGE * STAGE_B)   // 98304
#define KITER    128

__global__ __launch_bounds__(256, 2) void tc_gemm(float* __restrict__ outp, int flavor)
{
    extern __shared__ char smem[];
    const uint32_t sbase = smem_u32(smem);
    const int tid  = threadIdx.x;
    const int wid  = tid >> 5;
    const int lane = tid & 31;
    const int m0   = blockIdx.y * 128;
    const int n0   = blockIdx.x * 128;
    const int wm   = (wid & 3) * 32;
    const int wn   = (wid >> 2) * 64;

    const __nv_bfloat16 *aH, *aL, *bH, *bL;
    int mode;                                  // 0=Qquant 1=Kquant 2=V 3=out
    if (flavor == 1) { aH = g_ah; aL = g_al; bH = g_woh; bL = g_wol; mode = 3; }
    else {
        aH = g_xh; aL = g_xl; bH = g_wh; bL = g_wl;
        mode = (n0 < 2048) ? 0 : (n0 < 2560) ? 1 : 2;
    }
    const __nv_bfloat16* srcs[4] = {
        aH + (size_t)m0 * DMODEL, aL + (size_t)m0 * DMODEL,
        bH + (size_t)n0 * DMODEL, bL + (size_t)n0 * DMODEL };

    const int r0 = tid >> 1;
    const int s0 = tid & 1;

    const uint32_t aAddr = sbase + (wm + (lane & 15)) * GP + ((lane >> 4) << 4);
    const uint32_t bAddr = sbase + 2 * TILE_B +
        (wn + (lane & 7) + ((lane >> 4) & 1) * 8) * GP + (((lane >> 3) & 1) << 4);

    float acc[2][8][4];
#pragma unroll
    for (int mt = 0; mt < 2; mt++)
#pragma unroll
        for (int nt = 0; nt < 8; nt++)
#pragma unroll
            for (int i = 0; i < 4; i++) acc[mt][nt][i] = 0.f;

    auto load_stage = [&](int it) {
        const int kc = it * 16;
        const uint32_t db = sbase + (it & (NSTAGE - 1)) * STAGE_B;
        const uint32_t d0 = db + r0 * GP + s0 * 16;
        const size_t   so = (size_t)r0 * DMODEL + kc + s0 * 8;
#pragma unroll
        for (int t = 0; t < 4; t++)
            CP_ASYNC16(d0 + t * TILE_B, (const char*)(srcs[t] + so));
    };

    load_stage(0); CP_COMMIT();
    load_stage(1); CP_COMMIT();
    load_stage(2); CP_COMMIT();

    for (int it = 0; it < KITER; it++) {
        CP_WAIT(2);
        __syncthreads();
        if (it + 3 < KITER) load_stage(it + 3);
        CP_COMMIT();

        const uint32_t off = (it & (NSTAGE - 1)) * STAGE_B;
        const uint32_t ab = aAddr + off;
        const uint32_t bb = bAddr + off;
        uint32_t ah[2][4], al[2][4], bh[4][4], bl[4][4];
#pragma unroll
        for (int mt = 0; mt < 2; mt++) {
            LDSM4(ah[mt], ab + mt * (16 * GP));
            LDSM4(al[mt], ab + mt * (16 * GP) + TILE_B);
        }
#pragma unroll
        for (int np = 0; np < 4; np++) {
            LDSM4(bh[np], bb + np * (16 * GP));
            LDSM4(bl[np], bb + np * (16 * GP) + TILE_B);
        }
        // ---- term-major: 16 independent MMAs between accumulator reuses ----
#pragma unroll
        for (int mt = 0; mt < 2; mt++)
#pragma unroll
            for (int nt = 0; nt < 8; nt++)
                mma_bf16(acc[mt][nt], ah[mt],
                         bh[nt >> 1][(nt & 1) * 2], bh[nt >> 1][(nt & 1) * 2 + 1]);
#pragma unroll
        for (int mt = 0; mt < 2; mt++)
#pragma unroll
            for (int nt = 0; nt < 8; nt++)
                mma_bf16(acc[mt][nt], ah[mt],
                         bl[nt >> 1][(nt & 1) * 2], bl[nt >> 1][(nt & 1) * 2 + 1]);
#pragma unroll
        for (int mt = 0; mt < 2; mt++)
#pragma unroll
            for (int nt = 0; nt < 8; nt++)
                mma_bf16(acc[mt][nt], al[mt],
                         bh[nt >> 1][(nt & 1) * 2], bh[nt >> 1][(nt & 1) * 2 + 1]);
    }

    // ---- epilogue ----
    const int qrow = lane >> 2;
    const int qcol = (lane & 3) * 2;
#pragma unroll
    for (int mt = 0; mt < 2; mt++) {
#pragma unroll
        for (int h = 0; h < 2; h++) {
            const int row = m0 + wm + mt * 16 + qrow + h * 8;
            if (mode <= 1) {
                float am = 0.f;
#pragma unroll
                for (int nt = 0; nt < 8; nt++)
                    am = fmaxf(am, fmaxf(fabsf(acc[mt][nt][h * 2]),
                                         fabsf(acc[mt][nt][h * 2 + 1])));
                am = fmaxf(am, __shfl_xor_sync(0xffffffffu, am, 1));
                am = fmaxf(am, __shfl_xor_sync(0xffffffffu, am, 2));
                float scale = 127.f / fmaxf(am, 1e-6f);
#pragma unroll
                for (int nt = 0; nt < 8; nt++) {
                    int v0 = min(127, max(-127, __float2int_rn(acc[mt][nt][h * 2]     * scale)));
                    int v1 = min(127, max(-127, __float2int_rn(acc[mt][nt][h * 2 + 1] * scale)));
                    unsigned short pk = (unsigned short)((v0 & 255) | ((v1 & 255) << 8));
                    if (mode == 0)
                        *reinterpret_cast<unsigned short*>(
                            &g_q8[(size_t)row * DMODEL + n0 + wn + nt * 8 + qcol]) = pk;
                    else
                        *reinterpret_cast<unsigned short*>(
                            &g_k8[(size_t)row * DKV + (n0 - 2048) + wn + nt * 8 + qcol]) = pk;
                }
                if ((lane & 3) == 0) {
                    if (mode == 0) g_qs[row * NH  + ((n0 + wn) >> 6)]        = scale;
                    else           g_ks[row * NKV + ((n0 - 2048 + wn) >> 6)] = scale;
                }
            } else {
#pragma unroll
                for (int nt = 0; nt < 8; nt++) {
                    float2 v = make_float2(acc[mt][nt][h * 2], acc[mt][nt][h * 2 + 1]);
                    if (mode == 2)
                        *reinterpret_cast<float2*>(
                            &g_v[(size_t)row * DKV + (n0 - 2560) + wn + nt * 8 + qcol]) = v;
                    else
                        *reinterpret_cast<float2*>(
                            &outp[(size_t)row * DMODEL + n0 + wn + nt * 8 + qcol]) = v;
                }
            }
        }
    }
}

// =====================================================================
// Attention kernel (round-2 design; epilogue writes bf16 hi/lo)
// =====================================================================
__global__ __launch_bounds__(128) void attn_kernel()
{
    const int h    = blockIdx.y;
    const int qb   = gridDim.x - 1 - blockIdx.x;
    const int kvh  = h >> 2;
    const int tid  = threadIdx.x;
    const int warp = tid >> 5;
    const int lane = tid & 31;
    const int g    = lane >> 2;
    const int tg   = lane & 3;
    const int rbase = warp * 16;

    __shared__ int   qsm[64][20];
    __shared__ int   ksm[64][20];
    __shared__ float vsm[64][72];
    __shared__ float psm[64][68];
    __shared__ float qfac[64];
    __shared__ float kinv[64];

#pragma unroll
    for (int i = 0; i < 2; i++) {
        int idx = tid + i * 128;
        int row = idx >> 2;
        int seg = idx & 3;
        int4 v = *reinterpret_cast<const int4*>(
            &g_q8[(size_t)(qb * 64 + row) * DMODEL + h * 64 + seg * 16]);
        *reinterpret_cast<int4*>(&qsm[row][seg * 4]) = v;
    }
    if (tid < 64) qfac[tid] = 0.125f / g_qs[(qb * 64 + tid) * NH + h];
    __syncthreads();

    int qa[2][4];
#pragma unroll
    for (int s = 0; s < 2; s++) {
        qa[s][0] = qsm[rbase + g    ][s * 8 + tg];
        qa[s][1] = qsm[rbase + g + 8][s * 8 + tg];
        qa[s][2] = qsm[rbase + g    ][s * 8 + 4 + tg];
        qa[s][3] = qsm[rbase + g + 8][s * 8 + 4 + tg];
    }

    const int   rowA = rbase + g, rowB = rowA + 8;
    const float qfA  = qfac[rowA], qfB = qfac[rowB];
    const int   qgA  = qb * 64 + rowA, qgB = qb * 64 + rowB;

    float acc[8][4];
#pragma unroll
    for (int nt = 0; nt < 8; nt++)
#pragma unroll
        for (int i = 0; i < 4; i++) acc[nt][i] = 0.f;
    float m_runA = NEG_INF, m_runB = NEG_INF;
    float l_runA = 0.f,     l_runB = 0.f;

    for (int j = 0; j <= qb; j++) {
#pragma unroll
        for (int i = 0; i < 2; i++) {
            int idx = tid + i * 128;
            int row = idx >> 2;
            int seg = idx & 3;
            int4 v = *reinterpret_cast<const int4*>(
                &g_k8[(size_t)(j * 64 + row) * DKV + kvh * 64 + seg * 16]);
            *reinterpret_cast<int4*>(&ksm[row][seg * 4]) = v;
        }
        if (tid < 64) kinv[tid] = 1.f / g_ks[(j * 64 + tid) * NKV + kvh];
#pragma unroll
        for (int i = 0; i < 8; i++) {
            int idx = tid + i * 128;
            int row = idx >> 4;
            int c4  = (idx & 15) << 2;
            float4 vv = *reinterpret_cast<const float4*>(
                &g_v[(size_t)(j * 64 + row) * DKV + kvh * 64 + c4]);
            vv.x = tf32r(vv.x); vv.y = tf32r(vv.y);
            vv.z = tf32r(vv.z); vv.w = tf32r(vv.w);
            *reinterpret_cast<float4*>(&vsm[row][c4]) = vv;
        }
        __syncthreads();

        int sc[8][4];
#pragma unroll
        for (int nt = 0; nt < 8; nt++) {
            sc[nt][0] = sc[nt][1] = sc[nt][2] = sc[nt][3] = 0;
#pragma unroll
            for (int s = 0; s < 2; s++) {
                int b0 = ksm[nt * 8 + g][s * 8 + tg];
                int b1 = ksm[nt * 8 + g][s * 8 + 4 + tg];
                mma_s8(sc[nt], qa[s], b0, b1);
            }
        }

        const bool maskblk = (j == qb);
        float sv[8][4];
        float mxA = NEG_INF, mxB = NEG_INF;
#pragma unroll
        for (int nt = 0; nt < 8; nt++) {
            int colbase = nt * 8 + tg * 2;
            float2 kv = *reinterpret_cast<const float2*>(&kinv[colbase]);
            float s0 = (float)sc[nt][0] * qfA * kv.x;
            float s1 = (float)sc[nt][1] * qfA * kv.y;
            float s2 = (float)sc[nt][2] * qfB * kv.x;
            float s3 = (float)sc[nt][3] * qfB * kv.y;
            if (maskblk) {
                int col = j * 64 + colbase;
                if (col     > qgA) s0 = NEG_INF;
                if (col + 1 > qgA) s1 = NEG_INF;
                if (col     > qgB) s2 = NEG_INF;
                if (col + 1 > qgB) s3 = NEG_INF;
            }
            sv[nt][0] = s0; sv[nt][1] = s1; sv[nt][2] = s2; sv[nt][3] = s3;
            mxA = fmaxf(mxA, fmaxf(s0, s1));
            mxB = fmaxf(mxB, fmaxf(s2, s3));
        }
        mxA = fmaxf(mxA, __shfl_xor_sync(0xffffffffu, mxA, 1));
        mxA = fmaxf(mxA, __shfl_xor_sync(0xffffffffu, mxA, 2));
        mxB = fmaxf(mxB, __shfl_xor_sync(0xffffffffu, mxB, 1));
        mxB = fmaxf(mxB, __shfl_xor_sync(0xffffffffu, mxB, 2));

        float mA = fmaxf(m_runA, mxA);
        float mB = fmaxf(m_runB, mxB);
        float aA = __expf(m_runA - mA);
        float aB = __expf(m_runB - mB);
        m_runA = mA; m_runB = mB;

        float sumA = 0.f, sumB = 0.f;
#pragma unroll
        for (int nt = 0; nt < 8; nt++) {
            int colbase = nt * 8 + tg * 2;
            float p0 = __expf(sv[nt][0] - mA);
            float p1 = __expf(sv[nt][1] - mA);
            float p2 = __expf(sv[nt][2] - mB);
            float p3 = __expf(sv[nt][3] - mB);
            sumA += p0 + p1; sumB += p2 + p3;
            float2 w0 = make_float2(tf32r(p0), tf32r(p1));
            float2 w1 = make_float2(tf32r(p2), tf32r(p3));
            *reinterpret_cast<float2*>(&psm[rowA][colbase]) = w0;
            *reinterpret_cast<float2*>(&psm[rowB][colbase]) = w1;
        }
        sumA += __shfl_xor_sync(0xffffffffu, sumA, 1);
        sumA += __shfl_xor_sync(0xffffffffu, sumA, 2);
        sumB += __shfl_xor_sync(0xffffffffu, sumB, 1);
        sumB += __shfl_xor_sync(0xffffffffu, sumB, 2);
        l_runA = l_runA * aA + sumA;
        l_runB = l_runB * aB + sumB;

#pragma unroll
        for (int nt = 0; nt < 8; nt++) {
            acc[nt][0] *= aA; acc[nt][1] *= aA;
            acc[nt][2] *= aB; acc[nt][3] *= aB;
        }

        __syncwarp();

#pragma unroll
        for (int ks = 0; ks < 8; ks++) {
            unsigned pa0 = __float_as_uint(psm[rowA][ks * 8 + tg]);
            unsigned pa1 = __float_as_uint(psm[rowB][ks * 8 + tg]);
            unsigned pa2 = __float_as_uint(psm[rowA][ks * 8 + 4 + tg]);
            unsigned pa3 = __float_as_uint(psm[rowB][ks * 8 + 4 + tg]);
#pragma unroll
            for (int nt = 0; nt < 8; nt++) {
                unsigned b0 = __float_as_uint(vsm[ks * 8 + tg    ][nt * 8 + g]);
                unsigned b1 = __float_as_uint(vsm[ks * 8 + tg + 4][nt * 8 + g]);
                mma_tf32(acc[nt], pa0, pa1, pa2, pa3, b0, b1);
            }
        }

        __syncthreads();
    }

    // ---- epilogue: write bf16 hi/lo for the tensor-core out-projection ----
    float ilA = 1.f / l_runA, ilB = 1.f / l_runB;
#pragma unroll
    for (int nt = 0; nt < 8; nt++) {
        int colbase = nt * 8 + tg * 2;
        float oA0 = acc[nt][0] * ilA, oA1 = acc[nt][1] * ilA;
        float oB0 = acc[nt][2] * ilB, oB1 = acc[nt][3] * ilB;
        size_t pA = (size_t)qgA * DMODEL + h * 64 + colbase;
        size_t pB = (size_t)qgB * DMODEL + h * 64 + colbase;
        __nv_bfloat162 hA, hB, lA, lB;
        hA.x = __float2bfloat16(oA0); hA.y = __float2bfloat16(oA1);
        hB.x = __float2bfloat16(oB0); hB.y = __float2bfloat16(oB1);
        lA.x = __float2bfloat16(oA0 - __bfloat162float(hA.x));
        lA.y = __float2bfloat16(oA1 - __bfloat162float(hA.y));
        lB.x = __float2bfloat16(oB0 - __bfloat162float(hB.x));
        lB.y = __float2bfloat16(oB1 - __bfloat162float(hB.y));
        *reinterpret_cast<__nv_bfloat162*>(&g_ah[pA]) = hA;
        *reinterpret_cast<__nv_bfloat162*>(&g_al[pA]) = lA;
        *reinterpret_cast<__nv_bfloat162*>(&g_ah[pB]) = hB;
        *reinterpret_cast<__nv_bfloat162*>(&g_al[pB]) = lB;
    }
}

// =====================================================================
extern "C" void kernel_launch(void* const* d_in, const int* in_sizes, int n_in,
                              void* d_out, int out_size)
{
    const float* x  = (const float*)d_in[0];
    const float* Wq = (const float*)d_in[1];
    const float* Wk = (const float*)d_in[2];
    const float* Wv = (const float*)d_in[3];
    const float* Wo = (const float*)d_in[4];
    float* out = (float*)d_out;

    cudaFuncSetAttribute(tc_gemm, cudaFuncAttributeMaxDynamicSharedMemorySize, SMEM_DYN);

    prep_kernel<<<592, 256>>>(x, Wq, Wk, Wv, Wo);
    tc_gemm<<<dim3(24, 16), 256, SMEM_DYN>>>(nullptr, 0);   // QKV + quant
    attn_kernel<<<dim3(32, 32), 128>>>();
    tc_gemm<<<dim3(16, 16), 256, SMEM_DYN>>>(out, 1);       // output projection
}

// round 10
// speedup vs baseline: 1.0723x; 1.0089x over previous
#include <cuda_runtime.h>
#include <cuda_fp16.h>
#include <cstdint>

#define S_LEN   2048
#define DMODEL  2048
#define DKV     512
#define NH      32
#define NKV     8
#define HD      64

// ---------------- scratch (static device globals; no allocation) ----------------
__device__ __align__(16) int8_t g_q8[S_LEN * DMODEL];   // 4 MB
__device__ float  g_qs[S_LEN * NH];
__device__ __align__(16) int8_t g_k8[S_LEN * DKV];      // 1 MB
__device__ float  g_ks[S_LEN * NKV];
__device__ __align__(16) float  g_v [S_LEN * DKV];      // 4 MB

// fp16 hi/lo split buffers
__device__ __align__(16) __half g_xh[S_LEN * DMODEL],   g_xl[S_LEN * DMODEL];
__device__ __align__(16) __half g_wh[3072 * DMODEL],    g_wl[3072 * DMODEL];
__device__ __align__(16) __half g_woh[DMODEL * DMODEL], g_wol[DMODEL * DMODEL];
__device__ __align__(16) __half g_ah[S_LEN * DMODEL],   g_al[S_LEN * DMODEL];

#define NEG_INF (__int_as_float(0xff800000))

// =====================================================================
// helpers
// =====================================================================
__device__ __forceinline__ void mma_f16(float* c, const uint32_t* a,
                                        uint32_t b0, uint32_t b1) {
    asm("mma.sync.aligned.m16n8k16.row.col.f32.f16.f16.f32 "
        "{%0,%1,%2,%3}, {%4,%5,%6,%7}, {%8,%9}, {%0,%1,%2,%3};"
        : "+f"(c[0]), "+f"(c[1]), "+f"(c[2]), "+f"(c[3])
        : "r"(a[0]), "r"(a[1]), "r"(a[2]), "r"(a[3]), "r"(b0), "r"(b1));
}

__device__ __forceinline__ void mma_s8(int* c, const int* a, int b0, int b1) {
    asm("mma.sync.aligned.m16n8k32.row.col.s32.s8.s8.s32 "
        "{%0,%1,%2,%3}, {%4,%5,%6,%7}, {%8,%9}, {%0,%1,%2,%3};"
        : "+r"(c[0]), "+r"(c[1]), "+r"(c[2]), "+r"(c[3])
        : "r"(a[0]), "r"(a[1]), "r"(a[2]), "r"(a[3]), "r"(b0), "r"(b1));
}

__device__ __forceinline__ void mma_tf32(float* c, unsigned a0, unsigned a1,
                                         unsigned a2, unsigned a3,
                                         unsigned b0, unsigned b1) {
    asm("mma.sync.aligned.m16n8k8.row.col.f32.tf32.tf32.f32 "
        "{%0,%1,%2,%3}, {%4,%5,%6,%7}, {%8,%9}, {%0,%1,%2,%3};"
        : "+f"(c[0]), "+f"(c[1]), "+f"(c[2]), "+f"(c[3])
        : "r"(a0), "r"(a1), "r"(a2), "r"(a3), "r"(b0), "r"(b1));
}

__device__ __forceinline__ float tf32r(float x) {
    unsigned u;
    asm("cvt.rna.tf32.f32 %0, %1;" : "=r"(u) : "f"(x));
    return __uint_as_float(u);
}

#define LDSM4(r, a) \
    asm volatile("ldmatrix.sync.aligned.m8n8.x4.shared.b16 {%0,%1,%2,%3}, [%4];" \
                 : "=r"((r)[0]), "=r"((r)[1]), "=r"((r)[2]), "=r"((r)[3]) : "r"(a))

#define CP_ASYNC16(dst, src) \
    asm volatile("cp.async.ca.shared.global [%0], [%1], 16;" :: "r"(dst), "l"(src))
#define CP_COMMIT() asm volatile("cp.async.commit_group;")
#define CP_WAIT(n)  asm volatile("cp.async.wait_group %0;" :: "n"(n))

__device__ __forceinline__ uint32_t smem_u32(const void* p) {
    uint32_t a;
    asm("{ .reg .u64 t; cvta.to.shared.u64 t, %1; cvt.u32.u64 %0, t; }" : "=r"(a) : "l"(p));
    return a;
}

// =====================================================================
// Prep: split fp32 inputs into fp16 hi/lo pairs (memory-bound)
// =====================================================================
__device__ __forceinline__ void split4(float4 v, __half* dh, __half* dl, size_t e) {
    __half h0 = __float2half_rn(v.x), h1 = __float2half_rn(v.y);
    __half h2 = __float2half_rn(v.z), h3 = __float2half_rn(v.w);
    __half2 a, b;
    a.x = h0; a.y = h1; b.x = h2; b.y = h3;
    *reinterpret_cast<__half2*>(dh + e)     = a;
    *reinterpret_cast<__half2*>(dh + e + 2) = b;
    __half2 c, d;
    c.x = __float2half_rn(v.x - __half2float(h0));
    c.y = __float2half_rn(v.y - __half2float(h1));
    d.x = __float2half_rn(v.z - __half2float(h2));
    d.y = __float2half_rn(v.w - __half2float(h3));
    *reinterpret_cast<__half2*>(dl + e)     = c;
    *reinterpret_cast<__half2*>(dl + e + 2) = d;
}

__global__ __launch_bounds__(256) void prep_kernel(
    const float* __restrict__ x, const float* __restrict__ Wq,
    const float* __restrict__ Wk, const float* __restrict__ Wv,
    const float* __restrict__ Wo)
{
    const int NX = S_LEN * DMODEL / 4;
    const int NW = 3072 * DMODEL / 4;
    const int NO = DMODEL * DMODEL / 4;
    const int total = NX + NW + NO;
    for (int i = blockIdx.x * blockDim.x + threadIdx.x; i < total;
         i += gridDim.x * blockDim.x) {
        if (i < NX) {
            float4 v = reinterpret_cast<const float4*>(x)[i];
            split4(v, g_xh, g_xl, (size_t)i * 4);
        } else if (i < NX + NW) {
            int j = i - NX;
            int row = j >> 9;
            int c4  = j & 511;
            float4 v;
            if (row < 2048)      v = reinterpret_cast<const float4*>(Wq)[row * 512 + c4];
            else if (row < 2560) v = reinterpret_cast<const float4*>(Wk)[(row - 2048) * 512 + c4];
            else                 v = reinterpret_cast<const float4*>(Wv)[(row - 2560) * 512 + c4];
            split4(v, g_wh, g_wl, (size_t)j * 4);
        } else {
            int j = i - NX - NW;
            float4 v = reinterpret_cast<const float4*>(Wo)[j];
            split4(v, g_woh, g_wol, (size_t)j * 4);
        }
    }
}

// =====================================================================
// Tensor-core GEMM v6: fp16 hi/lo. Q/K tiles: 3 terms (quantization-
// sensitive). V and out-projection tiles: 2 terms, C = (Ah+Al)*Bh.
// 4-stage cp.async pipeline, one sync per K-iter, 128x128 CTA, 2 CTA/SM.
// =====================================================================
#define GP       48
#define TILE_B   6144          // 128 * 48
#define STAGE_B  24576         // 4 tiles
#define NSTAGE   4
#define SMEM_DYN (NSTAGE * STAGE_B)   // 98304
#define KITER    128

__global__ __launch_bounds__(256, 2) void tc_gemm(float* __restrict__ outp, int flavor)
{
    extern __shared__ char smem[];
    const uint32_t sbase = smem_u32(smem);
    const int tid  = threadIdx.x;
    const int wid  = tid >> 5;
    const int lane = tid & 31;
    const int m0   = blockIdx.y * 128;
    const int n0   = blockIdx.x * 128;
    const int wm   = (wid & 3) * 32;
    const int wn   = (wid >> 2) * 64;

    const __half *aH, *aL, *bH, *bL;
    int mode;                                  // 0=Qquant 1=Kquant 2=V 3=out
    if (flavor == 1) { aH = g_ah; aL = g_al; bH = g_woh; bL = g_wol; mode = 3; }
    else {
        aH = g_xh; aL = g_xl; bH = g_wh; bL = g_wl;
        mode = (n0 < 2048) ? 0 : (n0 < 2560) ? 1 : 2;
    }
    const bool three_term = (mode <= 1);       // Q/K need full precision
    const __half* srcs[4] = {
        aH + (size_t)m0 * DMODEL, aL + (size_t)m0 * DMODEL,
        bH + (size_t)n0 * DMODEL, bL + (size_t)n0 * DMODEL };

    const int r0 = tid >> 1;
    const int s0 = tid & 1;

    const uint32_t aAddr = sbase + (wm + (lane & 15)) * GP + ((lane >> 4) << 4);
    const uint32_t bAddr = sbase + 2 * TILE_B +
        (wn + (lane & 7) + ((lane >> 4) & 1) * 8) * GP + (((lane >> 3) & 1) << 4);

    float acc[2][8][4];
#pragma unroll
    for (int mt = 0; mt < 2; mt++)
#pragma unroll
        for (int nt = 0; nt < 8; nt++)
#pragma unroll
            for (int i = 0; i < 4; i++) acc[mt][nt][i] = 0.f;

    auto load_stage = [&](int it) {
        const int kc = it * 16;
        const uint32_t db = sbase + (it & (NSTAGE - 1)) * STAGE_B;
        const uint32_t d0 = db + r0 * GP + s0 * 16;
        const size_t   so = (size_t)r0 * DMODEL + kc + s0 * 8;
        CP_ASYNC16(d0,              (const char*)(srcs[0] + so));
        CP_ASYNC16(d0 + TILE_B,     (const char*)(srcs[1] + so));
        CP_ASYNC16(d0 + 2 * TILE_B, (const char*)(srcs[2] + so));
        if (three_term)
            CP_ASYNC16(d0 + 3 * TILE_B, (const char*)(srcs[3] + so));
    };

    load_stage(0); CP_COMMIT();
    load_stage(1); CP_COMMIT();
    load_stage(2); CP_COMMIT();

    for (int it = 0; it < KITER; it++) {
        CP_WAIT(2);
        __syncthreads();
        if (it + 3 < KITER) load_stage(it + 3);
        CP_COMMIT();

        const uint32_t off = (it & (NSTAGE - 1)) * STAGE_B;
        const uint32_t ab = aAddr + off;
        const uint32_t bb = bAddr + off;
        uint32_t ah[2][4], al[2][4], bh[4][4];
#pragma unroll
        for (int mt = 0; mt < 2; mt++) {
            LDSM4(ah[mt], ab + mt * (16 * GP));
            LDSM4(al[mt], ab + mt * (16 * GP) + TILE_B);
        }
#pragma unroll
        for (int np = 0; np < 4; np++)
            LDSM4(bh[np], bb + np * (16 * GP));

        // term 1: Ah * Bh
#pragma unroll
        for (int mt = 0; mt < 2; mt++)
#pragma unroll
            for (int nt = 0; nt < 8; nt++)
                mma_f16(acc[mt][nt], ah[mt],
                        bh[nt >> 1][(nt & 1) * 2], bh[nt >> 1][(nt & 1) * 2 + 1]);
        // term 2: Al * Bh   (together: A * Bh)
#pragma unroll
        for (int mt = 0; mt < 2; mt++)
#pragma unroll
            for (int nt = 0; nt < 8; nt++)
                mma_f16(acc[mt][nt], al[mt],
                        bh[nt >> 1][(nt & 1) * 2], bh[nt >> 1][(nt & 1) * 2 + 1]);
        // term 3 (Q/K only): Ah * Bl
        if (three_term) {
            uint32_t bl[4][4];
#pragma unroll
            for (int np = 0; np < 4; np++)
                LDSM4(bl[np], bb + np * (16 * GP) + TILE_B);
#pragma unroll
            for (int mt = 0; mt < 2; mt++)
#pragma unroll
                for (int nt = 0; nt < 8; nt++)
                    mma_f16(acc[mt][nt], ah[mt],
                            bl[nt >> 1][(nt & 1) * 2], bl[nt >> 1][(nt & 1) * 2 + 1]);
        }
    }

    // ---- epilogue ----
    const int qrow = lane >> 2;
    const int qcol = (lane & 3) * 2;
#pragma unroll
    for (int mt = 0; mt < 2; mt++) {
#pragma unroll
        for (int h = 0; h < 2; h++) {
            const int row = m0 + wm + mt * 16 + qrow + h * 8;
            if (mode <= 1) {
                float am = 0.f;
#pragma unroll
                for (int nt = 0; nt < 8; nt++)
                    am = fmaxf(am, fmaxf(fabsf(acc[mt][nt][h * 2]),
                                         fabsf(acc[mt][nt][h * 2 + 1])));
                am = fmaxf(am, __shfl_xor_sync(0xffffffffu, am, 1));
                am = fmaxf(am, __shfl_xor_sync(0xffffffffu, am, 2));
                float scale = 127.f / fmaxf(am, 1e-6f);
#pragma unroll
                for (int nt = 0; nt < 8; nt++) {
                    int v0 = min(127, max(-127, __float2int_rn(acc[mt][nt][h * 2]     * scale)));
                    int v1 = min(127, max(-127, __float2int_rn(acc[mt][nt][h * 2 + 1] * scale)));
                    unsigned short pk = (unsigned short)((v0 & 255) | ((v1 & 255) << 8));
                    if (mode == 0)
                        *reinterpret_cast<unsigned short*>(
                            &g_q8[(size_t)row * DMODEL + n0 + wn + nt * 8 + qcol]) = pk;
                    else
                        *reinterpret_cast<unsigned short*>(
                            &g_k8[(size_t)row * DKV + (n0 - 2048) + wn + nt * 8 + qcol]) = pk;
                }
                if ((lane & 3) == 0) {
                    if (mode == 0) g_qs[row * NH  + ((n0 + wn) >> 6)]        = scale;
                    else           g_ks[row * NKV + ((n0 - 2048 + wn) >> 6)] = scale;
                }
            } else {
#pragma unroll
                for (int nt = 0; nt < 8; nt++) {
                    float2 v = make_float2(acc[mt][nt][h * 2], acc[mt][nt][h * 2 + 1]);
                    if (mode == 2)
                        *reinterpret_cast<float2*>(
                            &g_v[(size_t)row * DKV + (n0 - 2560) + wn + nt * 8 + qcol]) = v;
                    else
                        *reinterpret_cast<float2*>(
                            &outp[(size_t)row * DMODEL + n0 + wn + nt * 8 + qcol]) = v;
                }
            }
        }
    }
}

// =====================================================================
// Attention kernel (round-2 design; epilogue writes fp16 hi/lo)
// =====================================================================
__global__ __launch_bounds__(128) void attn_kernel()
{
    const int h    = blockIdx.y;
    const int qb   = gridDim.x - 1 - blockIdx.x;
    const int kvh  = h >> 2;
    const int tid  = threadIdx.x;
    const int warp = tid >> 5;
    const int lane = tid & 31;
    const int g    = lane >> 2;
    const int tg   = lane & 3;
    const int rbase = warp * 16;

    __shared__ int   qsm[64][20];
    __shared__ int   ksm[64][20];
    __shared__ float vsm[64][72];
    __shared__ float psm[64][68];
    __shared__ float qfac[64];
    __shared__ float kinv[64];

#pragma unroll
    for (int i = 0; i < 2; i++) {
        int idx = tid + i * 128;
        int row = idx >> 2;
        int seg = idx & 3;
        int4 v = *reinterpret_cast<const int4*>(
            &g_q8[(size_t)(qb * 64 + row) * DMODEL + h * 64 + seg * 16]);
        *reinterpret_cast<int4*>(&qsm[row][seg * 4]) = v;
    }
    if (tid < 64) qfac[tid] = 0.125f / g_qs[(qb * 64 + tid) * NH + h];
    __syncthreads();

    int qa[2][4];
#pragma unroll
    for (int s = 0; s < 2; s++) {
        qa[s][0] = qsm[rbase + g    ][s * 8 + tg];
        qa[s][1] = qsm[rbase + g + 8][s * 8 + tg];
        qa[s][2] = qsm[rbase + g    ][s * 8 + 4 + tg];
        qa[s][3] = qsm[rbase + g + 8][s * 8 + 4 + tg];
    }

    const int   rowA = rbase + g, rowB = rowA + 8;
    const float qfA  = qfac[rowA], qfB = qfac[rowB];
    const int   qgA  = qb * 64 + rowA, qgB = qb * 64 + rowB;

    float acc[8][4];
#pragma unroll
    for (int nt = 0; nt < 8; nt++)
#pragma unroll
        for (int i = 0; i < 4; i++) acc[nt][i] = 0.f;
    float m_runA = NEG_INF, m_runB = NEG_INF;
    float l_runA = 0.f,     l_runB = 0.f;

    for (int j = 0; j <= qb; j++) {
#pragma unroll
        for (int i = 0; i < 2; i++) {
            int idx = tid + i * 128;
            int row = idx >> 2;
            int seg = idx & 3;
            int4 v = *reinterpret_cast<const int4*>(
                &g_k8[(size_t)(j * 64 + row) * DKV + kvh * 64 + seg * 16]);
            *reinterpret_cast<int4*>(&ksm[row][seg * 4]) = v;
        }
        if (tid < 64) kinv[tid] = 1.f / g_ks[(j * 64 + tid) * NKV + kvh];
#pragma unroll
        for (int i = 0; i < 8; i++) {
            int idx = tid + i * 128;
            int row = idx >> 4;
            int c4  = (idx & 15) << 2;
            float4 vv = *reinterpret_cast<const float4*>(
                &g_v[(size_t)(j * 64 + row) * DKV + kvh * 64 + c4]);
            vv.x = tf32r(vv.x); vv.y = tf32r(vv.y);
            vv.z = tf32r(vv.z); vv.w = tf32r(vv.w);
            *reinterpret_cast<float4*>(&vsm[row][c4]) = vv;
        }
        __syncthreads();

        int sc[8][4];
#pragma unroll
        for (int nt = 0; nt < 8; nt++) {
            sc[nt][0] = sc[nt][1] = sc[nt][2] = sc[nt][3] = 0;
#pragma unroll
            for (int s = 0; s < 2; s++) {
                int b0 = ksm[nt * 8 + g][s * 8 + tg];
                int b1 = ksm[nt * 8 + g][s * 8 + 4 + tg];
                mma_s8(sc[nt], qa[s], b0, b1);
            }
        }

        const bool maskblk = (j == qb);
        float sv[8][4];
        float mxA = NEG_INF, mxB = NEG_INF;
#pragma unroll
        for (int nt = 0; nt < 8; nt++) {
            int colbase = nt * 8 + tg * 2;
            float2 kv = *reinterpret_cast<const float2*>(&kinv[colbase]);
            float s0 = (float)sc[nt][0] * qfA * kv.x;
            float s1 = (float)sc[nt][1] * qfA * kv.y;
            float s2 = (float)sc[nt][2] * qfB * kv.x;
            float s3 = (float)sc[nt][3] * qfB * kv.y;
            if (maskblk) {
                int col = j * 64 + colbase;
                if (col     > qgA) s0 = NEG_INF;
                if (col + 1 > qgA) s1 = NEG_INF;
                if (col     > qgB) s2 = NEG_INF;
                if (col + 1 > qgB) s3 = NEG_INF;
            }
            sv[nt][0] = s0; sv[nt][1] = s1; sv[nt][2] = s2; sv[nt][3] = s3;
            mxA = fmaxf(mxA, fmaxf(s0, s1));
            mxB = fmaxf(mxB, fmaxf(s2, s3));
        }
        mxA = fmaxf(mxA, __shfl_xor_sync(0xffffffffu, mxA, 1));
        mxA = fmaxf(mxA, __shfl_xor_sync(0xffffffffu, mxA, 2));
        mxB = fmaxf(mxB, __shfl_xor_sync(0xffffffffu, mxB, 1));
        mxB = fmaxf(mxB, __shfl_xor_sync(0xffffffffu, mxB, 2));

        float mA = fmaxf(m_runA, mxA);
        float mB = fmaxf(m_runB, mxB);
        float aA = __expf(m_runA - mA);
        float aB = __expf(m_runB - mB);
        m_runA = mA; m_runB = mB;

        float sumA = 0.f, sumB = 0.f;
#pragma unroll
        for (int nt = 0; nt < 8; nt++) {
            int colbase = nt * 8 + tg * 2;
            float p0 = __expf(sv[nt][0] - mA);
            float p1 = __expf(sv[nt][1] - mA);
            float p2 = __expf(sv[nt][2] - mB);
            float p3 = __expf(sv[nt][3] - mB);
            sumA += p0 + p1; sumB += p2 + p3;
            float2 w0 = make_float2(tf32r(p0), tf32r(p1));
            float2 w1 = make_float2(tf32r(p2), tf32r(p3));
            *reinterpret_cast<float2*>(&psm[rowA][colbase]) = w0;
            *reinterpret_cast<float2*>(&psm[rowB][colbase]) = w1;
        }
        sumA += __shfl_xor_sync(0xffffffffu, sumA, 1);
        sumA += __shfl_xor_sync(0xffffffffu, sumA, 2);
        sumB += __shfl_xor_sync(0xffffffffu, sumB, 1);
        sumB += __shfl_xor_sync(0xffffffffu, sumB, 2);
        l_runA = l_runA * aA + sumA;
        l_runB = l_runB * aB + sumB;

#pragma unroll
        for (int nt = 0; nt < 8; nt++) {
            acc[nt][0] *= aA; acc[nt][1] *= aA;
            acc[nt][2] *= aB; acc[nt][3] *= aB;
        }

        __syncwarp();

#pragma unroll
        for (int ks = 0; ks < 8; ks++) {
            unsigned pa0 = __float_as_uint(psm[rowA][ks * 8 + tg]);
            unsigned pa1 = __float_as_uint(psm[rowB][ks * 8 + tg]);
            unsigned pa2 = __float_as_uint(psm[rowA][ks * 8 + 4 + tg]);
            unsigned pa3 = __float_as_uint(psm[rowB][ks * 8 + 4 + tg]);
#pragma unroll
            for (int nt = 0; nt < 8; nt++) {
                unsigned b0 = __float_as_uint(vsm[ks * 8 + tg    ][nt * 8 + g]);
                unsigned b1 = __float_as_uint(vsm[ks * 8 + tg + 4][nt * 8 + g]);
                mma_tf32(acc[nt], pa0, pa1, pa2, pa3, b0, b1);
            }
        }

        __syncthreads();
    }

    // ---- epilogue: write fp16 hi/lo for the tensor-core out-projection ----
    float ilA = 1.f / l_runA, ilB = 1.f / l_runB;
#pragma unroll
    for (int nt = 0; nt < 8; nt++) {
        int colbase = nt * 8 + tg * 2;
        float oA0 = acc[nt][0] * ilA, oA1 = acc[nt][1] * ilA;
        float oB0 = acc[nt][2] * ilB, oB1 = acc[nt][3] * ilB;
        size_t pA = (size_t)qgA * DMODEL + h * 64 + colbase;
        size_t pB = (size_t)qgB * DMODEL + h * 64 + colbase;
        __half2 hA, hB, lA, lB;
        hA.x = __float2half_rn(oA0); hA.y = __float2half_rn(oA1);
        hB.x = __float2half_rn(oB0); hB.y = __float2half_rn(oB1);
        lA.x = __float2half_rn(oA0 - __half2float(hA.x));
        lA.y = __float2half_rn(oA1 - __half2float(hA.y));
        lB.x = __float2half_rn(oB0 - __half2float(hB.x));
        lB.y = __float2half_rn(oB1 - __half2float(hB.y));
        *reinterpret_cast<__half2*>(&g_ah[pA]) = hA;
        *reinterpret_cast<__half2*>(&g_al[pA]) = lA;
        *reinterpret_cast<__half2*>(&g_ah[pB]) = hB;
        *reinterpret_cast<__half2*>(&g_al[pB]) = lB;
    }
}

// =====================================================================
extern "C" void kernel_launch(void* const* d_in, const int* in_sizes, int n_in,
                              void* d_out, int out_size)
{
    const float* x  = (const float*)d_in[0];
    const float* Wq = (const float*)d_in[1];
    const float* Wk = (const float*)d_in[2];
    const float* Wv = (const float*)d_in[3];
    const float* Wo = (const float*)d_in[4];
    float* out = (float*)d_out;

    cudaFuncSetAttribute(tc_gemm, cudaFuncAttributeMaxDynamicSharedMemorySize, SMEM_DYN);

    prep_kernel<<<592, 256>>>(x, Wq, Wk, Wv, Wo);
    tc_gemm<<<dim3(24, 16), 256, SMEM_DYN>>>(nullptr, 0);   // QKV + quant
    attn_kernel<<<dim3(32, 32), 128>>>();
    tc_gemm<<<dim3(16, 16), 256, SMEM_DYN>>>(out, 1);       // output projection
}

// round 11
// speedup vs baseline: 1.1881x; 1.1080x over previous
#include <cuda_runtime.h>
#include <cuda_fp16.h>
#include <cstdint>

#define S_LEN   2048
#define DMODEL  2048
#define DKV     512
#define NH      32
#define NKV     8
#define HD      64

// ---------------- scratch (static device globals; no allocation) ----------------
__device__ __align__(16) int8_t g_q8[S_LEN * DMODEL];   // 4 MB
__device__ float  g_qs[S_LEN * NH];
__device__ __align__(16) int8_t g_k8[S_LEN * DKV];      // 1 MB
__device__ float  g_ks[S_LEN * NKV];
__device__ __align__(16) float  g_v [S_LEN * DKV];      // 4 MB

// fp16 hi/lo split buffers
__device__ __align__(16) __half g_xh[S_LEN * DMODEL],   g_xl[S_LEN * DMODEL];
__device__ __align__(16) __half g_wh[3072 * DMODEL],    g_wl[3072 * DMODEL];
__device__ __align__(16) __half g_woh[DMODEL * DMODEL], g_wol[DMODEL * DMODEL];
__device__ __align__(16) __half g_ah[S_LEN * DMODEL],   g_al[S_LEN * DMODEL];

#define NEG_INF (__int_as_float(0xff800000))

// =====================================================================
// helpers
// =====================================================================
__device__ __forceinline__ void mma_f16(float* c, const uint32_t* a,
                                        uint32_t b0, uint32_t b1) {
    asm("mma.sync.aligned.m16n8k16.row.col.f32.f16.f16.f32 "
        "{%0,%1,%2,%3}, {%4,%5,%6,%7}, {%8,%9}, {%0,%1,%2,%3};"
        : "+f"(c[0]), "+f"(c[1]), "+f"(c[2]), "+f"(c[3])
        : "r"(a[0]), "r"(a[1]), "r"(a[2]), "r"(a[3]), "r"(b0), "r"(b1));
}

__device__ __forceinline__ void mma_f16s(float* c, uint32_t a0, uint32_t a1,
                                         uint32_t a2, uint32_t a3,
                                         uint32_t b0, uint32_t b1) {
    asm("mma.sync.aligned.m16n8k16.row.col.f32.f16.f16.f32 "
        "{%0,%1,%2,%3}, {%4,%5,%6,%7}, {%8,%9}, {%0,%1,%2,%3};"
        : "+f"(c[0]), "+f"(c[1]), "+f"(c[2]), "+f"(c[3])
        : "r"(a0), "r"(a1), "r"(a2), "r"(a3), "r"(b0), "r"(b1));
}

__device__ __forceinline__ void mma_s8(int* c, const int* a, int b0, int b1) {
    asm("mma.sync.aligned.m16n8k32.row.col.s32.s8.s8.s32 "
        "{%0,%1,%2,%3}, {%4,%5,%6,%7}, {%8,%9}, {%0,%1,%2,%3};"
        : "+r"(c[0]), "+r"(c[1]), "+r"(c[2]), "+r"(c[3])
        : "r"(a[0]), "r"(a[1]), "r"(a[2]), "r"(a[3]), "r"(b0), "r"(b1));
}

#define LDSM4(r, a) \
    asm volatile("ldmatrix.sync.aligned.m8n8.x4.shared.b16 {%0,%1,%2,%3}, [%4];" \
                 : "=r"((r)[0]), "=r"((r)[1]), "=r"((r)[2]), "=r"((r)[3]) : "r"(a))

#define LDSM2T(r0, r1, a) \
    asm volatile("ldmatrix.sync.aligned.m8n8.x2.trans.shared.b16 {%0,%1}, [%2];" \
                 : "=r"(r0), "=r"(r1) : "r"(a))

#define CP_ASYNC16(dst, src) \
    asm volatile("cp.async.ca.shared.global [%0], [%1], 16;" :: "r"(dst), "l"(src))
#define CP_COMMIT() asm volatile("cp.async.commit_group;")
#define CP_WAIT(n)  asm volatile("cp.async.wait_group %0;" :: "n"(n))

__device__ __forceinline__ uint32_t smem_u32(const void* p) {
    uint32_t a;
    asm("{ .reg .u64 t; cvta.to.shared.u64 t, %1; cvt.u32.u64 %0, t; }" : "=r"(a) : "l"(p));
    return a;
}

// =====================================================================
// Prep: split fp32 inputs into fp16 hi/lo pairs (memory-bound)
// =====================================================================
__device__ __forceinline__ void split4(float4 v, __half* dh, __half* dl, size_t e) {
    __half h0 = __float2half_rn(v.x), h1 = __float2half_rn(v.y);
    __half h2 = __float2half_rn(v.z), h3 = __float2half_rn(v.w);
    __half2 a, b;
    a.x = h0; a.y = h1; b.x = h2; b.y = h3;
    *reinterpret_cast<__half2*>(dh + e)     = a;
    *reinterpret_cast<__half2*>(dh + e + 2) = b;
    __half2 c, d;
    c.x = __float2half_rn(v.x - __half2float(h0));
    c.y = __float2half_rn(v.y - __half2float(h1));
    d.x = __float2half_rn(v.z - __half2float(h2));
    d.y = __float2half_rn(v.w - __half2float(h3));
    *reinterpret_cast<__half2*>(dl + e)     = c;
    *reinterpret_cast<__half2*>(dl + e + 2) = d;
}

__global__ __launch_bounds__(256) void prep_kernel(
    const float* __restrict__ x, const float* __restrict__ Wq,
    const float* __restrict__ Wk, const float* __restrict__ Wv,
    const float* __restrict__ Wo)
{
    const int NX = S_LEN * DMODEL / 4;
    const int NW = 3072 * DMODEL / 4;
    const int NO = DMODEL * DMODEL / 4;
    const int total = NX + NW + NO;
    for (int i = blockIdx.x * blockDim.x + threadIdx.x; i < total;
         i += gridDim.x * blockDim.x) {
        if (i < NX) {
            float4 v = reinterpret_cast<const float4*>(x)[i];
            split4(v, g_xh, g_xl, (size_t)i * 4);
        } else if (i < NX + NW) {
            int j = i - NX;
            int row = j >> 9;
            int c4  = j & 511;
            float4 v;
            if (row < 2048)      v = reinterpret_cast<const float4*>(Wq)[row * 512 + c4];
            else if (row < 2560) v = reinterpret_cast<const float4*>(Wk)[(row - 2048) * 512 + c4];
            else                 v = reinterpret_cast<const float4*>(Wv)[(row - 2560) * 512 + c4];
            split4(v, g_wh, g_wl, (size_t)j * 4);
        } else {
            int j = i - NX - NW;
            float4 v = reinterpret_cast<const float4*>(Wo)[j];
            split4(v, g_woh, g_wol, (size_t)j * 4);
        }
    }
}

// =====================================================================
// Tensor-core GEMM: fp16 hi/lo. Q/K tiles 3-term; V/out tiles 2-term.
// 4-stage cp.async pipeline, 128x128 CTA, 2 CTA/SM.
// Grid: blockIdx.x = m-tile, blockIdx.y = n-tile (V tiles launch LAST).
// =====================================================================
#define GP       48
#define TILE_B   6144          // 128 * 48
#define STAGE_B  24576         // 4 tiles
#define NSTAGE   4
#define SMEM_DYN (NSTAGE * STAGE_B)   // 98304
#define KITER    128

__global__ __launch_bounds__(256, 2) void tc_gemm(float* __restrict__ outp, int flavor)
{
    extern __shared__ char smem[];
    const uint32_t sbase = smem_u32(smem);
    const int tid  = threadIdx.x;
    const int wid  = tid >> 5;
    const int lane = tid & 31;
    const int m0   = blockIdx.x * 128;     // x = m-tile (fast axis)
    const int n0   = blockIdx.y * 128;     // y = n-tile (V tiles last)
    const int wm   = (wid & 3) * 32;
    const int wn   = (wid >> 2) * 64;

    const __half *aH, *aL, *bH, *bL;
    int mode;                                  // 0=Qquant 1=Kquant 2=V 3=out
    if (flavor == 1) { aH = g_ah; aL = g_al; bH = g_woh; bL = g_wol; mode = 3; }
    else {
        aH = g_xh; aL = g_xl; bH = g_wh; bL = g_wl;
        mode = (n0 < 2048) ? 0 : (n0 < 2560) ? 1 : 2;
    }
    const bool three_term = (mode <= 1);
    const __half* srcs[4] = {
        aH + (size_t)m0 * DMODEL, aL + (size_t)m0 * DMODEL,
        bH + (size_t)n0 * DMODEL, bL + (size_t)n0 * DMODEL };

    const int r0 = tid >> 1;
    const int s0 = tid & 1;

    const uint32_t aAddr = sbase + (wm + (lane & 15)) * GP + ((lane >> 4) << 4);
    const uint32_t bAddr = sbase + 2 * TILE_B +
        (wn + (lane & 7) + ((lane >> 4) & 1) * 8) * GP + (((lane >> 3) & 1) << 4);

    float acc[2][8][4];
#pragma unroll
    for (int mt = 0; mt < 2; mt++)
#pragma unroll
        for (int nt = 0; nt < 8; nt++)
#pragma unroll
            for (int i = 0; i < 4; i++) acc[mt][nt][i] = 0.f;

    auto load_stage = [&](int it) {
        const int kc = it * 16;
        const uint32_t db = sbase + (it & (NSTAGE - 1)) * STAGE_B;
        const uint32_t d0 = db + r0 * GP + s0 * 16;
        const size_t   so = (size_t)r0 * DMODEL + kc + s0 * 8;
        CP_ASYNC16(d0,              (const char*)(srcs[0] + so));
        CP_ASYNC16(d0 + TILE_B,     (const char*)(srcs[1] + so));
        CP_ASYNC16(d0 + 2 * TILE_B, (const char*)(srcs[2] + so));
        if (three_term)
            CP_ASYNC16(d0 + 3 * TILE_B, (const char*)(srcs[3] + so));
    };

    load_stage(0); CP_COMMIT();
    load_stage(1); CP_COMMIT();
    load_stage(2); CP_COMMIT();

    for (int it = 0; it < KITER; it++) {
        CP_WAIT(2);
        __syncthreads();
        if (it + 3 < KITER) load_stage(it + 3);
        CP_COMMIT();

        const uint32_t off = (it & (NSTAGE - 1)) * STAGE_B;
        const uint32_t ab = aAddr + off;
        const uint32_t bb = bAddr + off;
        uint32_t ah[2][4], al[2][4], bh[4][4];
#pragma unroll
        for (int mt = 0; mt < 2; mt++) {
            LDSM4(ah[mt], ab + mt * (16 * GP));
            LDSM4(al[mt], ab + mt * (16 * GP) + TILE_B);
        }
#pragma unroll
        for (int np = 0; np < 4; np++)
            LDSM4(bh[np], bb + np * (16 * GP));

#pragma unroll
        for (int mt = 0; mt < 2; mt++)
#pragma unroll
            for (int nt = 0; nt < 8; nt++)
                mma_f16(acc[mt][nt], ah[mt],
                        bh[nt >> 1][(nt & 1) * 2], bh[nt >> 1][(nt & 1) * 2 + 1]);
#pragma unroll
        for (int mt = 0; mt < 2; mt++)
#pragma unroll
            for (int nt = 0; nt < 8; nt++)
                mma_f16(acc[mt][nt], al[mt],
                        bh[nt >> 1][(nt & 1) * 2], bh[nt >> 1][(nt & 1) * 2 + 1]);
        if (three_term) {
            uint32_t bl[4][4];
#pragma unroll
            for (int np = 0; np < 4; np++)
                LDSM4(bl[np], bb + np * (16 * GP) + TILE_B);
#pragma unroll
            for (int mt = 0; mt < 2; mt++)
#pragma unroll
                for (int nt = 0; nt < 8; nt++)
                    mma_f16(acc[mt][nt], ah[mt],
                            bl[nt >> 1][(nt & 1) * 2], bl[nt >> 1][(nt & 1) * 2 + 1]);
        }
    }

    // ---- epilogue ----
    const int qrow = lane >> 2;
    const int qcol = (lane & 3) * 2;
#pragma unroll
    for (int mt = 0; mt < 2; mt++) {
#pragma unroll
        for (int h = 0; h < 2; h++) {
            const int row = m0 + wm + mt * 16 + qrow + h * 8;
            if (mode <= 1) {
                float am = 0.f;
#pragma unroll
                for (int nt = 0; nt < 8; nt++)
                    am = fmaxf(am, fmaxf(fabsf(acc[mt][nt][h * 2]),
                                         fabsf(acc[mt][nt][h * 2 + 1])));
                am = fmaxf(am, __shfl_xor_sync(0xffffffffu, am, 1));
                am = fmaxf(am, __shfl_xor_sync(0xffffffffu, am, 2));
                float scale = 127.f / fmaxf(am, 1e-6f);
#pragma unroll
                for (int nt = 0; nt < 8; nt++) {
                    int v0 = min(127, max(-127, __float2int_rn(acc[mt][nt][h * 2]     * scale)));
                    int v1 = min(127, max(-127, __float2int_rn(acc[mt][nt][h * 2 + 1] * scale)));
                    unsigned short pk = (unsigned short)((v0 & 255) | ((v1 & 255) << 8));
                    if (mode == 0)
                        *reinterpret_cast<unsigned short*>(
                            &g_q8[(size_t)row * DMODEL + n0 + wn + nt * 8 + qcol]) = pk;
                    else
                        *reinterpret_cast<unsigned short*>(
                            &g_k8[(size_t)row * DKV + (n0 - 2048) + wn + nt * 8 + qcol]) = pk;
                }
                if ((lane & 3) == 0) {
                    if (mode == 0) g_qs[row * NH  + ((n0 + wn) >> 6)]        = scale;
                    else           g_ks[row * NKV + ((n0 - 2048 + wn) >> 6)] = scale;
                }
            } else {
#pragma unroll
                for (int nt = 0; nt < 8; nt++) {
                    float2 v = make_float2(acc[mt][nt][h * 2], acc[mt][nt][h * 2 + 1]);
                    if (mode == 2)
                        *reinterpret_cast<float2*>(
                            &g_v[(size_t)row * DKV + (n0 - 2560) + wn + nt * 8 + qcol]) = v;
                    else
                        *reinterpret_cast<float2*>(
                            &outp[(size_t)row * DMODEL + n0 + wn + nt * 8 + qcol]) = v;
                }
            }
        }
    }
}

// =====================================================================
// Attention kernel: s8 scores + fp16 m16n8k16 PV (V via ldmatrix.trans)
// =====================================================================
__global__ __launch_bounds__(128) void attn_kernel()
{
    const int h    = blockIdx.y;
    const int qb   = gridDim.x - 1 - blockIdx.x;
    const int kvh  = h >> 2;
    const int tid  = threadIdx.x;
    const int warp = tid >> 5;
    const int lane = tid & 31;
    const int g    = lane >> 2;
    const int tg   = lane & 3;
    const int rbase = warp * 16;

    __shared__ int    qsm[64][20];
    __shared__ int    ksm[64][20];
    __shared__ __align__(16) __half vsm[64][72];   // [key][dim], pitch 144B (16B-mult)
    __shared__ __align__(16) __half psm[64][72];   // [row][key]
    __shared__ float  qfac[64];
    __shared__ float  kinv[64];

#pragma unroll
    for (int i = 0; i < 2; i++) {
        int idx = tid + i * 128;
        int row = idx >> 2;
        int seg = idx & 3;
        int4 v = *reinterpret_cast<const int4*>(
            &g_q8[(size_t)(qb * 64 + row) * DMODEL + h * 64 + seg * 16]);
        *reinterpret_cast<int4*>(&qsm[row][seg * 4]) = v;
    }
    if (tid < 64) qfac[tid] = 0.125f / g_qs[(qb * 64 + tid) * NH + h];
    __syncthreads();

    int qa[2][4];
#pragma unroll
    for (int s = 0; s < 2; s++) {
        qa[s][0] = qsm[rbase + g    ][s * 8 + tg];
        qa[s][1] = qsm[rbase + g + 8][s * 8 + tg];
        qa[s][2] = qsm[rbase + g    ][s * 8 + 4 + tg];
        qa[s][3] = qsm[rbase + g + 8][s * 8 + 4 + tg];
    }

    const int   rowA = rbase + g, rowB = rowA + 8;
    const float qfA  = qfac[rowA], qfB = qfac[rowB];
    const int   qgA  = qb * 64 + rowA, qgB = qb * 64 + rowB;

    // ldmatrix row address for V (lanes 0-15 select keys; pitch 144B)
    const uint32_t vbase = smem_u32(&vsm[0][0]) + (lane & 15) * 144;
    const uint32_t pbase = smem_u32(&psm[0][0]);

    float acc[8][4];
#pragma unroll
    for (int nt = 0; nt < 8; nt++)
#pragma unroll
        for (int i = 0; i < 4; i++) acc[nt][i] = 0.f;
    float m_runA = NEG_INF, m_runB = NEG_INF;
    float l_runA = 0.f,     l_runB = 0.f;

    for (int j = 0; j <= qb; j++) {
#pragma unroll
        for (int i = 0; i < 2; i++) {
            int idx = tid + i * 128;
            int row = idx >> 2;
            int seg = idx & 3;
            int4 v = *reinterpret_cast<const int4*>(
                &g_k8[(size_t)(j * 64 + row) * DKV + kvh * 64 + seg * 16]);
            *reinterpret_cast<int4*>(&ksm[row][seg * 4]) = v;
        }
        if (tid < 64) kinv[tid] = 1.f / g_ks[(j * 64 + tid) * NKV + kvh];
        // V block -> fp16 smem [key][dim]
#pragma unroll
        for (int i = 0; i < 8; i++) {
            int idx = tid + i * 128;
            int row = idx >> 4;
            int c4  = (idx & 15) << 2;
            float4 vv = *reinterpret_cast<const float4*>(
                &g_v[(size_t)(j * 64 + row) * DKV + kvh * 64 + c4]);
            __half2 h01 = __floats2half2_rn(vv.x, vv.y);
            __half2 h23 = __floats2half2_rn(vv.z, vv.w);
            *reinterpret_cast<__half2*>(&vsm[row][c4])     = h01;
            *reinterpret_cast<__half2*>(&vsm[row][c4 + 2]) = h23;
        }
        __syncthreads();

        int sc[8][4];
#pragma unroll
        for (int nt = 0; nt < 8; nt++) {
            sc[nt][0] = sc[nt][1] = sc[nt][2] = sc[nt][3] = 0;
#pragma unroll
            for (int s = 0; s < 2; s++) {
                int b0 = ksm[nt * 8 + g][s * 8 + tg];
                int b1 = ksm[nt * 8 + g][s * 8 + 4 + tg];
                mma_s8(sc[nt], qa[s], b0, b1);
            }
        }

        const bool maskblk = (j == qb);
        float sv[8][4];
        float mxA = NEG_INF, mxB = NEG_INF;
#pragma unroll
        for (int nt = 0; nt < 8; nt++) {
            int colbase = nt * 8 + tg * 2;
            float2 kv = *reinterpret_cast<const float2*>(&kinv[colbase]);
            float s0 = (float)sc[nt][0] * qfA * kv.x;
            float s1 = (float)sc[nt][1] * qfA * kv.y;
            float s2 = (float)sc[nt][2] * qfB * kv.x;
            float s3 = (float)sc[nt][3] * qfB * kv.y;
            if (maskblk) {
                int col = j * 64 + colbase;
                if (col     > qgA) s0 = NEG_INF;
                if (col + 1 > qgA) s1 = NEG_INF;
                if (col     > qgB) s2 = NEG_INF;
                if (col + 1 > qgB) s3 = NEG_INF;
            }
            sv[nt][0] = s0; sv[nt][1] = s1; sv[nt][2] = s2; sv[nt][3] = s3;
            mxA = fmaxf(mxA, fmaxf(s0, s1));
            mxB = fmaxf(mxB, fmaxf(s2, s3));
        }
        mxA = fmaxf(mxA, __shfl_xor_sync(0xffffffffu, mxA, 1));
        mxA = fmaxf(mxA, __shfl_xor_sync(0xffffffffu, mxA, 2));
        mxB = fmaxf(mxB, __shfl_xor_sync(0xffffffffu, mxB, 1));
        mxB = fmaxf(mxB, __shfl_xor_sync(0xffffffffu, mxB, 2));

        float mA = fmaxf(m_runA, mxA);
        float mB = fmaxf(m_runB, mxB);
        float aA = __expf(m_runA - mA);
        float aB = __expf(m_runB - mB);
        m_runA = mA; m_runB = mB;

        float sumA = 0.f, sumB = 0.f;
#pragma unroll
        for (int nt = 0; nt < 8; nt++) {
            int colbase = nt * 8 + tg * 2;
            float p0 = __expf(sv[nt][0] - mA);
            float p1 = __expf(sv[nt][1] - mA);
            float p2 = __expf(sv[nt][2] - mB);
            float p3 = __expf(sv[nt][3] - mB);
            sumA += p0 + p1; sumB += p2 + p3;
            *reinterpret_cast<__half2*>(&psm[rowA][colbase]) = __floats2half2_rn(p0, p1);
            *reinterpret_cast<__half2*>(&psm[rowB][colbase]) = __floats2half2_rn(p2, p3);
        }
        sumA += __shfl_xor_sync(0xffffffffu, sumA, 1);
        sumA += __shfl_xor_sync(0xffffffffu, sumA, 2);
        sumB += __shfl_xor_sync(0xffffffffu, sumB, 1);
        sumB += __shfl_xor_sync(0xffffffffu, sumB, 2);
        l_runA = l_runA * aA + sumA;
        l_runB = l_runB * aB + sumB;

#pragma unroll
        for (int nt = 0; nt < 8; nt++) {
            acc[nt][0] *= aA; acc[nt][1] *= aA;
            acc[nt][2] *= aB; acc[nt][3] *= aB;
        }

        __syncwarp();   // psm rows are warp-private

        // ---- PV: 4 k-steps of m16n8k16 fp16, V via ldmatrix.x2.trans ----
#pragma unroll
        for (int ks = 0; ks < 4; ks++) {
            uint32_t a0 = *reinterpret_cast<const uint32_t*>(&psm[rowA][ks * 16 + tg * 2]);
            uint32_t a1 = *reinterpret_cast<const uint32_t*>(&psm[rowB][ks * 16 + tg * 2]);
            uint32_t a2 = *reinterpret_cast<const uint32_t*>(&psm[rowA][ks * 16 + 8 + tg * 2]);
            uint32_t a3 = *reinterpret_cast<const uint32_t*>(&psm[rowB][ks * 16 + 8 + tg * 2]);
            const uint32_t vrow = vbase + ks * (16 * 144);
#pragma unroll
            for (int nt = 0; nt < 8; nt++) {
                uint32_t b0, b1;
                LDSM2T(b0, b1, vrow + nt * 16);
                mma_f16s(acc[nt], a0, a1, a2, a3, b0, b1);
            }
        }

        __syncthreads();
    }

    // ---- epilogue: write fp16 hi/lo for the tensor-core out-projection ----
    float ilA = 1.f / l_runA, ilB = 1.f / l_runB;
#pragma unroll
    for (int nt = 0; nt < 8; nt++) {
        int colbase = nt * 8 + tg * 2;
        float oA0 = acc[nt][0] * ilA, oA1 = acc[nt][1] * ilA;
        float oB0 = acc[nt][2] * ilB, oB1 = acc[nt][3] * ilB;
        size_t pA = (size_t)qgA * DMODEL + h * 64 + colbase;
        size_t pB = (size_t)qgB * DMODEL + h * 64 + colbase;
        __half2 hA, hB, lA, lB;
        hA.x = __float2half_rn(oA0); hA.y = __float2half_rn(oA1);
        hB.x = __float2half_rn(oB0); hB.y = __float2half_rn(oB1);
        lA.x = __float2half_rn(oA0 - __half2float(hA.x));
        lA.y = __float2half_rn(oA1 - __half2float(hA.y));
        lB.x = __float2half_rn(oB0 - __half2float(hB.x));
        lB.y = __float2half_rn(oB1 - __half2float(hB.y));
        *reinterpret_cast<__half2*>(&g_ah[pA]) = hA;
        *reinterpret_cast<__half2*>(&g_al[pA]) = lA;
        *reinterpret_cast<__half2*>(&g_ah[pB]) = hB;
        *reinterpret_cast<__half2*>(&g_al[pB]) = lB;
    }
}

// =====================================================================
extern "C" void kernel_launch(void* const* d_in, const int* in_sizes, int n_in,
                              void* d_out, int out_size)
{
    const float* x  = (const float*)d_in[0];
    const float* Wq = (const float*)d_in[1];
    const float* Wk = (const float*)d_in[2];
    const float* Wv = (const float*)d_in[3];
    const float* Wo = (const float*)d_in[4];
    float* out = (float*)d_out;

    cudaFuncSetAttribute(tc_gemm, cudaFuncAttributeMaxDynamicSharedMemorySize, SMEM_DYN);

    prep_kernel<<<592, 256>>>(x, Wq, Wk, Wv, Wo);
    tc_gemm<<<dim3(16, 24), 256, SMEM_DYN>>>(nullptr, 0);   // QKV (V tiles last)
    attn_kernel<<<dim3(32, 32), 128>>>();
    tc_gemm<<<dim3(16, 16), 256, SMEM_DYN>>>(out, 1);       // output projection
}

// round 13
// speedup vs baseline: 1.3015x; 1.0955x over previous
#include <cuda_runtime.h>
#include <cuda_fp16.h>
#include <cstdint>

#define S_LEN   2048
#define DMODEL  2048
#define DKV     512
#define NH      32
#define NKV     8
#define HD      64

// ---------------- scratch (static device globals; no allocation) ----------------
__device__ __align__(16) int8_t g_q8[S_LEN * DMODEL];   // 4 MB
__device__ float  g_qs[S_LEN * NH];
__device__ __align__(16) int8_t g_k8[S_LEN * DKV];      // 1 MB
__device__ float  g_ks[S_LEN * NKV];
__device__ __align__(16) float  g_v [S_LEN * DKV];      // 4 MB

// fp16 hi/lo split buffers
__device__ __align__(16) __half g_xh[S_LEN * DMODEL],   g_xl[S_LEN * DMODEL];
__device__ __align__(16) __half g_wh[3072 * DMODEL],    g_wl[3072 * DMODEL];
__device__ __align__(16) __half g_woh[DMODEL * DMODEL];
__device__ __align__(16) __half g_ah[S_LEN * DMODEL];

#define NEG_INF (__int_as_float(0xff800000))

// =====================================================================
// helpers
// =====================================================================
__device__ __forceinline__ void mma_f16(float* c, const uint32_t* a,
                                        uint32_t b0, uint32_t b1) {
    asm("mma.sync.aligned.m16n8k16.row.col.f32.f16.f16.f32 "
        "{%0,%1,%2,%3}, {%4,%5,%6,%7}, {%8,%9}, {%0,%1,%2,%3};"
        : "+f"(c[0]), "+f"(c[1]), "+f"(c[2]), "+f"(c[3])
        : "r"(a[0]), "r"(a[1]), "r"(a[2]), "r"(a[3]), "r"(b0), "r"(b1));
}

__device__ __forceinline__ void mma_f16s(float* c, uint32_t a0, uint32_t a1,
                                         uint32_t a2, uint32_t a3,
                                         uint32_t b0, uint32_t b1) {
    asm("mma.sync.aligned.m16n8k16.row.col.f32.f16.f16.f32 "
        "{%0,%1,%2,%3}, {%4,%5,%6,%7}, {%8,%9}, {%0,%1,%2,%3};"
        : "+f"(c[0]), "+f"(c[1]), "+f"(c[2]), "+f"(c[3])
        : "r"(a0), "r"(a1), "r"(a2), "r"(a3), "r"(b0), "r"(b1));
}

__device__ __forceinline__ void mma_s8(int* c, const int* a, int b0, int b1) {
    asm("mma.sync.aligned.m16n8k32.row.col.s32.s8.s8.s32 "
        "{%0,%1,%2,%3}, {%4,%5,%6,%7}, {%8,%9}, {%0,%1,%2,%3};"
        : "+r"(c[0]), "+r"(c[1]), "+r"(c[2]), "+r"(c[3])
        : "r"(a[0]), "r"(a[1]), "r"(a[2]), "r"(a[3]), "r"(b0), "r"(b1));
}

#define LDSM4(r, a) \
    asm volatile("ldmatrix.sync.aligned.m8n8.x4.shared.b16 {%0,%1,%2,%3}, [%4];" \
                 : "=r"((r)[0]), "=r"((r)[1]), "=r"((r)[2]), "=r"((r)[3]) : "r"(a))

#define LDSM2T(r0, r1, a) \
    asm volatile("ldmatrix.sync.aligned.m8n8.x2.trans.shared.b16 {%0,%1}, [%2];" \
                 : "=r"(r0), "=r"(r1) : "r"(a))

#define CP_ASYNC16(dst, src) \
    asm volatile("cp.async.ca.shared.global [%0], [%1], 16;" :: "r"(dst), "l"(src))
#define CP_COMMIT() asm volatile("cp.async.commit_group;")
#define CP_WAIT(n)  asm volatile("cp.async.wait_group %0;" :: "n"(n))

__device__ __forceinline__ uint32_t smem_u32(const void* p) {
    uint32_t a;
    asm("{ .reg .u64 t; cvta.to.shared.u64 t, %1; cvt.u32.u64 %0, t; }" : "=r"(a) : "l"(p));
    return a;
}

// =====================================================================
// Prep: split fp32 inputs into fp16 hi/lo pairs (Wo: hi only, out is 1-term)
// =====================================================================
__device__ __forceinline__ void split4(float4 v, __half* dh, __half* dl, size_t e) {
    __half h0 = __float2half_rn(v.x), h1 = __float2half_rn(v.y);
    __half h2 = __float2half_rn(v.z), h3 = __float2half_rn(v.w);
    __half2 a, b;
    a.x = h0; a.y = h1; b.x = h2; b.y = h3;
    *reinterpret_cast<__half2*>(dh + e)     = a;
    *reinterpret_cast<__half2*>(dh + e + 2) = b;
    __half2 c, d;
    c.x = __float2half_rn(v.x - __half2float(h0));
    c.y = __float2half_rn(v.y - __half2float(h1));
    d.x = __float2half_rn(v.z - __half2float(h2));
    d.y = __float2half_rn(v.w - __half2float(h3));
    *reinterpret_cast<__half2*>(dl + e)     = c;
    *reinterpret_cast<__half2*>(dl + e + 2) = d;
}

__global__ __launch_bounds__(256) void prep_kernel(
    const float* __restrict__ x, const float* __restrict__ Wq,
    const float* __restrict__ Wk, const float* __restrict__ Wv,
    const float* __restrict__ Wo)
{
    const int NX = S_LEN * DMODEL / 4;
    const int NW = 3072 * DMODEL / 4;
    const int NO = DMODEL * DMODEL / 4;
    const int total = NX + NW + NO;
    for (int i = blockIdx.x * blockDim.x + threadIdx.x; i < total;
         i += gridDim.x * blockDim.x) {
        if (i < NX) {
            float4 v = reinterpret_cast<const float4*>(x)[i];
            split4(v, g_xh, g_xl, (size_t)i * 4);
        } else if (i < NX + NW) {
            int j = i - NX;
            int row = j >> 9;
            int c4  = j & 511;
            float4 v;
            if (row < 2048)      v = reinterpret_cast<const float4*>(Wq)[row * 512 + c4];
            else if (row < 2560) v = reinterpret_cast<const float4*>(Wk)[(row - 2048) * 512 + c4];
            else                 v = reinterpret_cast<const float4*>(Wv)[(row - 2560) * 512 + c4];
            split4(v, g_wh, g_wl, (size_t)j * 4);
        } else {
            int j = i - NX - NW;
            float4 v = reinterpret_cast<const float4*>(Wo)[j];
            __half2 a, b;
            a = __floats2half2_rn(v.x, v.y);
            b = __floats2half2_rn(v.z, v.w);
            *reinterpret_cast<__half2*>(g_woh + (size_t)j * 4)     = a;
            *reinterpret_cast<__half2*>(g_woh + (size_t)j * 4 + 2) = b;
        }
    }
}

// =====================================================================
// Tensor-core GEMM: fp16 hi/lo split, variable term count per mode:
//   Q/K tiles: 3 terms (quantization-sensitive)
//   V tiles:   2 terms (A exact, B fp16)
//   out tiles: 1 term  (plain fp16 x fp16)
// 4-stage cp.async pipeline, 128x128 CTA, 2 CTA/SM.
// =====================================================================
#define GP       48
#define TILE_B   6144          // 128 * 48
#define STAGE_B  24576         // 4 tiles
#define NSTAGE   4
#define SMEM_DYN (NSTAGE * STAGE_B)   // 98304
#define KITER    128

__global__ __launch_bounds__(256, 2) void tc_gemm(float* __restrict__ outp, int flavor)
{
    extern __shared__ char smem[];
    const uint32_t sbase = smem_u32(smem);
    const int tid  = threadIdx.x;
    const int wid  = tid >> 5;
    const int lane = tid & 31;
    const int m0   = blockIdx.x * 128;     // x = m-tile (fast axis)
    const int n0   = blockIdx.y * 128;     // y = n-tile (V tiles last)
    const int wm   = (wid & 3) * 32;
    const int wn   = (wid >> 2) * 64;

    const __half *aH, *aL, *bH, *bL;
    int mode;                                  // 0=Qquant 1=Kquant 2=V 3=out
    if (flavor == 1) { aH = g_ah; aL = g_ah; bH = g_woh; bL = g_woh; mode = 3; }
    else {
        aH = g_xh; aL = g_xl; bH = g_wh; bL = g_wl;
        mode = (n0 < 2048) ? 0 : (n0 < 2560) ? 1 : 2;
    }
    const int nterms = (mode <= 1) ? 3 : (mode == 2) ? 2 : 1;
    const __half* srcs[4] = {
        aH + (size_t)m0 * DMODEL, aL + (size_t)m0 * DMODEL,
        bH + (size_t)n0 * DMODEL, bL + (size_t)n0 * DMODEL };

    const int r0 = tid >> 1;
    const int s0 = tid & 1;

    const uint32_t aAddr = sbase + (wm + (lane & 15)) * GP + ((lane >> 4) << 4);
    const uint32_t bAddr = sbase + 2 * TILE_B +
        (wn + (lane & 7) + ((lane >> 4) & 1) * 8) * GP + (((lane >> 3) & 1) << 4);

    float acc[2][8][4];
#pragma unroll
    for (int mt = 0; mt < 2; mt++)
#pragma unroll
        for (int nt = 0; nt < 8; nt++)
#pragma unroll
            for (int i = 0; i < 4; i++) acc[mt][nt][i] = 0.f;

    auto load_stage = [&](int it) {
        const int kc = it * 16;
        const uint32_t db = sbase + (it & (NSTAGE - 1)) * STAGE_B;
        const uint32_t d0 = db + r0 * GP + s0 * 16;
        const size_t   so = (size_t)r0 * DMODEL + kc + s0 * 8;
        CP_ASYNC16(d0,              (const char*)(srcs[0] + so));
        CP_ASYNC16(d0 + 2 * TILE_B, (const char*)(srcs[2] + so));
        if (nterms >= 2)
            CP_ASYNC16(d0 + TILE_B, (const char*)(srcs[1] + so));
        if (nterms == 3)
            CP_ASYNC16(d0 + 3 * TILE_B, (const char*)(srcs[3] + so));
    };

    load_stage(0); CP_COMMIT();
    load_stage(1); CP_COMMIT();
    load_stage(2); CP_COMMIT();

    for (int it = 0; it < KITER; it++) {
        CP_WAIT(2);
        __syncthreads();
        if (it + 3 < KITER) load_stage(it + 3);
        CP_COMMIT();

        const uint32_t off = (it & (NSTAGE - 1)) * STAGE_B;
        const uint32_t ab = aAddr + off;
        const uint32_t bb = bAddr + off;
        uint32_t ah[2][4], bh[4][4];
#pragma unroll
        for (int mt = 0; mt < 2; mt++)
            LDSM4(ah[mt], ab + mt * (16 * GP));
#pragma unroll
        for (int np = 0; np < 4; np++)
            LDSM4(bh[np], bb + np * (16 * GP));

        // term 1: Ah * Bh
#pragma unroll
        for (int mt = 0; mt < 2; mt++)
#pragma unroll
            for (int nt = 0; nt < 8; nt++)
                mma_f16(acc[mt][nt], ah[mt],
                        bh[nt >> 1][(nt & 1) * 2], bh[nt >> 1][(nt & 1) * 2 + 1]);
        // term 2: Al * Bh
        if (nterms >= 2) {
            uint32_t al[2][4];
#pragma unroll
            for (int mt = 0; mt < 2; mt++)
                LDSM4(al[mt], ab + mt * (16 * GP) + TILE_B);
#pragma unroll
            for (int mt = 0; mt < 2; mt++)
#pragma unroll
                for (int nt = 0; nt < 8; nt++)
                    mma_f16(acc[mt][nt], al[mt],
                            bh[nt >> 1][(nt & 1) * 2], bh[nt >> 1][(nt & 1) * 2 + 1]);
        }
        // term 3: Ah * Bl
        if (nterms == 3) {
            uint32_t bl[4][4];
#pragma unroll
            for (int np = 0; np < 4; np++)
                LDSM4(bl[np], bb + np * (16 * GP) + TILE_B);
#pragma unroll
            for (int mt = 0; mt < 2; mt++)
#pragma unroll
                for (int nt = 0; nt < 8; nt++)
                    mma_f16(acc[mt][nt], ah[mt],
                            bl[nt >> 1][(nt & 1) * 2], bl[nt >> 1][(nt & 1) * 2 + 1]);
        }
    }

    // ---- epilogue ----
    const int qrow = lane >> 2;
    const int qcol = (lane & 3) * 2;
#pragma unroll
    for (int mt = 0; mt < 2; mt++) {
#pragma unroll
        for (int h = 0; h < 2; h++) {
            const int row = m0 + wm + mt * 16 + qrow + h * 8;
            if (mode <= 1) {
                float am = 0.f;
#pragma unroll
                for (int nt = 0; nt < 8; nt++)
                    am = fmaxf(am, fmaxf(fabsf(acc[mt][nt][h * 2]),
                                         fabsf(acc[mt][nt][h * 2 + 1])));
                am = fmaxf(am, __shfl_xor_sync(0xffffffffu, am, 1));
                am = fmaxf(am, __shfl_xor_sync(0xffffffffu, am, 2));
                float scale = 127.f / fmaxf(am, 1e-6f);
#pragma unroll
                for (int nt = 0; nt < 8; nt++) {
                    int v0 = min(127, max(-127, __float2int_rn(acc[mt][nt][h * 2]     * scale)));
                    int v1 = min(127, max(-127, __float2int_rn(acc[mt][nt][h * 2 + 1] * scale)));
                    unsigned short pk = (unsigned short)((v0 & 255) | ((v1 & 255) << 8));
                    if (mode == 0)
                        *reinterpret_cast<unsigned short*>(
                            &g_q8[(size_t)row * DMODEL + n0 + wn + nt * 8 + qcol]) = pk;
                    else
                        *reinterpret_cast<unsigned short*>(
                            &g_k8[(size_t)row * DKV + (n0 - 2048) + wn + nt * 8 + qcol]) = pk;
                }
                if ((lane & 3) == 0) {
                    if (mode == 0) g_qs[row * NH  + ((n0 + wn) >> 6)]        = scale;
                    else           g_ks[row * NKV + ((n0 - 2048 + wn) >> 6)] = scale;
                }
            } else {
#pragma unroll
                for (int nt = 0; nt < 8; nt++) {
                    float2 v = make_float2(acc[mt][nt][h * 2], acc[mt][nt][h * 2 + 1]);
                    if (mode == 2)
                        *reinterpret_cast<float2*>(
                            &g_v[(size_t)row * DKV + (n0 - 2560) + wn + nt * 8 + qcol]) = v;
                    else
                        *reinterpret_cast<float2*>(
                            &outp[(size_t)row * DMODEL + n0 + wn + nt * 8 + qcol]) = v;
                }
            }
        }
    }
}

// =====================================================================
// Attention kernel: s8 scores + fp16 m16n8k16 PV (V via ldmatrix.trans)
// =====================================================================
__global__ __launch_bounds__(128) void attn_kernel()
{
    const int h    = blockIdx.y;
    const int qb   = gridDim.x - 1 - blockIdx.x;
    const int kvh  = h >> 2;
    const int tid  = threadIdx.x;
    const int warp = tid >> 5;
    const int lane = tid & 31;
    const int g    = lane >> 2;
    const int tg   = lane & 3;
    const int rbase = warp * 16;

    __shared__ int    qsm[64][20];
    __shared__ int    ksm[64][20];
    __shared__ __align__(16) __half vsm[64][72];   // [key][dim], pitch 144B
    __shared__ __align__(16) __half psm[64][72];   // [row][key]
    __shared__ float  qfac[64];
    __shared__ float  kinv[64];

#pragma unroll
    for (int i = 0; i < 2; i++) {
        int idx = tid + i * 128;
        int row = idx >> 2;
        int seg = idx & 3;
        int4 v = *reinterpret_cast<const int4*>(
            &g_q8[(size_t)(qb * 64 + row) * DMODEL + h * 64 + seg * 16]);
        *reinterpret_cast<int4*>(&qsm[row][seg * 4]) = v;
    }
    if (tid < 64) qfac[tid] = 0.125f / g_qs[(qb * 64 + tid) * NH + h];
    __syncthreads();

    int qa[2][4];
#pragma unroll
    for (int s = 0; s < 2; s++) {
        qa[s][0] = qsm[rbase + g    ][s * 8 + tg];
        qa[s][1] = qsm[rbase + g + 8][s * 8 + tg];
        qa[s][2] = qsm[rbase + g    ][s * 8 + 4 + tg];
        qa[s][3] = qsm[rbase + g + 8][s * 8 + 4 + tg];
    }

    const int   rowA = rbase + g, rowB = rowA + 8;
    const float qfA  = qfac[rowA], qfB = qfac[rowB];
    const int   qgA  = qb * 64 + rowA, qgB = qb * 64 + rowB;

    const uint32_t vbase = smem_u32(&vsm[0][0]) + (lane & 15) * 144;

    float acc[8][4];
#pragma unroll
    for (int nt = 0; nt < 8; nt++)
#pragma unroll
        for (int i = 0; i < 4; i++) acc[nt][i] = 0.f;
    float m_runA = NEG_INF, m_runB = NEG_INF;
    float l_runA = 0.f,     l_runB = 0.f;

    for (int j = 0; j <= qb; j++) {
#pragma unroll
        for (int i = 0; i < 2; i++) {
            int idx = tid + i * 128;
            int row = idx >> 2;
            int seg = idx & 3;
            int4 v = *reinterpret_cast<const int4*>(
                &g_k8[(size_t)(j * 64 + row) * DKV + kvh * 64 + seg * 16]);
            *reinterpret_cast<int4*>(&ksm[row][seg * 4]) = v;
        }
        if (tid < 64) kinv[tid] = 1.f / g_ks[(j * 64 + tid) * NKV + kvh];
#pragma unroll
        for (int i = 0; i < 8; i++) {
            int idx = tid + i * 128;
            int row = idx >> 4;
            int c4  = (idx & 15) << 2;
            float4 vv = *reinterpret_cast<const float4*>(
                &g_v[(size_t)(j * 64 + row) * DKV + kvh * 64 + c4]);
            *reinterpret_cast<__half2*>(&vsm[row][c4])     = __floats2half2_rn(vv.x, vv.y);
            *reinterpret_cast<__half2*>(&vsm[row][c4 + 2]) = __floats2half2_rn(vv.z, vv.w);
        }
        __syncthreads();

        int sc[8][4];
#pragma unroll
        for (int nt = 0; nt < 8; nt++) {
            sc[nt][0] = sc[nt][1] = sc[nt][2] = sc[nt][3] = 0;
#pragma unroll
            for (int s = 0; s < 2; s++) {
                int b0 = ksm[nt * 8 + g][s * 8 + tg];
                int b1 = ksm[nt * 8 + g][s * 8 + 4 + tg];
                mma_s8(sc[nt], qa[s], b0, b1);
            }
        }

        const bool maskblk = (j == qb);
        float sv[8][4];
        float mxA = NEG_INF, mxB = NEG_INF;
#pragma unroll
        for (int nt = 0; nt < 8; nt++) {
            int colbase = nt * 8 + tg * 2;
            float2 kv = *reinterpret_cast<const float2*>(&kinv[colbase]);
            float s0 = (float)sc[nt][0] * qfA * kv.x;
            float s1 = (float)sc[nt][1] * qfA * kv.y;
            float s2 = (float)sc[nt][2] * qfB * kv.x;
            float s3 = (float)sc[nt][3] * qfB * kv.y;
            if (maskblk) {
                int col = j * 64 + colbase;
                if (col     > qgA) s0 = NEG_INF;
                if (col + 1 > qgA) s1 = NEG_INF;
                if (col     > qgB) s2 = NEG_INF;
                if (col + 1 > qgB) s3 = NEG_INF;
            }
            sv[nt][0] = s0; sv[nt][1] = s1; sv[nt][2] = s2; sv[nt][3] = s3;
            mxA = fmaxf(mxA, fmaxf(s0, s1));
            mxB = fmaxf(mxB, fmaxf(s2, s3));
        }
        mxA = fmaxf(mxA, __shfl_xor_sync(0xffffffffu, mxA, 1));
        mxA = fmaxf(mxA, __shfl_xor_sync(0xffffffffu, mxA, 2));
        mxB = fmaxf(mxB, __shfl_xor_sync(0xffffffffu, mxB, 1));
        mxB = fmaxf(mxB, __shfl_xor_sync(0xffffffffu, mxB, 2));

        float mA = fmaxf(m_runA, mxA);
        float mB = fmaxf(m_runB, mxB);
        float aA = __expf(m_runA - mA);
        float aB = __expf(m_runB - mB);
        m_runA = mA; m_runB = mB;

        float sumA = 0.f, sumB = 0.f;
#pragma unroll
        for (int nt = 0; nt < 8; nt++) {
            int colbase = nt * 8 + tg * 2;
            float p0 = __expf(sv[nt][0] - mA);
            float p1 = __expf(sv[nt][1] - mA);
            float p2 = __expf(sv[nt][2] - mB);
            float p3 = __expf(sv[nt][3] - mB);
            sumA += p0 + p1; sumB += p2 + p3;
            *reinterpret_cast<__half2*>(&psm[rowA][colbase]) = __floats2half2_rn(p0, p1);
            *reinterpret_cast<__half2*>(&psm[rowB][colbase]) = __floats2half2_rn(p2, p3);
        }
        sumA += __shfl_xor_sync(0xffffffffu, sumA, 1);
        sumA += __shfl_xor_sync(0xffffffffu, sumA, 2);
        sumB += __shfl_xor_sync(0xffffffffu, sumB, 1);
        sumB += __shfl_xor_sync(0xffffffffu, sumB, 2);
        l_runA = l_runA * aA + sumA;
        l_runB = l_runB * aB + sumB;

#pragma unroll
        for (int nt = 0; nt < 8; nt++) {
            acc[nt][0] *= aA; acc[nt][1] *= aA;
            acc[nt][2] *= aB; acc[nt][3] *= aB;
        }

        __syncwarp();   // psm rows are warp-private

#pragma unroll
        for (int ks = 0; ks < 4; ks++) {
            uint32_t a0 = *reinterpret_cast<const uint32_t*>(&psm[rowA][ks * 16 + tg * 2]);
            uint32_t a1 = *reinterpret_cast<const uint32_t*>(&psm[rowB][ks * 16 + tg * 2]);
            uint32_t a2 = *reinterpret_cast<const uint32_t*>(&psm[rowA][ks * 16 + 8 + tg * 2]);
            uint32_t a3 = *reinterpret_cast<const uint32_t*>(&psm[rowB][ks * 16 + 8 + tg * 2]);
            const uint32_t vrow = vbase + ks * (16 * 144);
#pragma unroll
            for (int nt = 0; nt < 8; nt++) {
                uint32_t b0, b1;
                LDSM2T(b0, b1, vrow + nt * 16);
                mma_f16s(acc[nt], a0, a1, a2, a3, b0, b1);
            }
        }

        __syncthreads();
    }

    // ---- epilogue: fp16 (hi only — out-projection is 1-term) ----
    float ilA = 1.f / l_runA, ilB = 1.f / l_runB;
#pragma unroll
    for (int nt = 0; nt < 8; nt++) {
        int colbase = nt * 8 + tg * 2;
        float oA0 = acc[nt][0] * ilA, oA1 = acc[nt][1] * ilA;
        float oB0 = acc[nt][2] * ilB, oB1 = acc[nt][3] * ilB;
        size_t pA = (size_t)qgA * DMODEL + h * 64 + colbase;
        size_t pB = (size_t)qgB * DMODEL + h * 64 + colbase;
        *reinterpret_cast<__half2*>(&g_ah[pA]) = __floats2half2_rn(oA0, oA1);
        *reinterpret_cast<__half2*>(&g_ah[pB]) = __floats2half2_rn(oB0, oB1);
    }
}

// =====================================================================
extern "C" void kernel_launch(void* const* d_in, const int* in_sizes, int n_in,
                              void* d_out, int out_size)
{
    const float* x  = (const float*)d_in[0];
    const float* Wq = (const float*)d_in[1];
    const float* Wk = (const float*)d_in[2];
    const float* Wv = (const float*)d_in[3];
    const float* Wo = (const float*)d_in[4];
    float* out = (float*)d_out;

    cudaFuncSetAttribute(tc_gemm, cudaFuncAttributeMaxDynamicSharedMemorySize, SMEM_DYN);

    prep_kernel<<<592, 256>>>(x, Wq, Wk, Wv, Wo);
    tc_gemm<<<dim3(16, 24), 256, SMEM_DYN>>>(nullptr, 0);   // QKV (V tiles last)
    attn_kernel<<<dim3(32, 32), 128>>>();
    tc_gemm<<<dim3(16, 16), 256, SMEM_DYN>>>(out, 1);       // output projection, 1-term
}

// round 14
// speedup vs baseline: 1.4287x; 1.0977x over previous
#include <cuda_runtime.h>
#include <cuda_fp16.h>
#include <cstdint>

#define S_LEN   2048
#define DMODEL  2048
#define DKV     512
#define NH      32
#define NKV     8
#define HD      64

// ---------------- scratch (static device globals; no allocation) ----------------
__device__ __align__(16) int8_t g_q8[S_LEN * DMODEL];   // 4 MB
__device__ __align__(16) int8_t g_k8[S_LEN * DKV];      // 1 MB
__device__ __align__(16) float  g_qsi[NH  * S_LEN];     // 0.125/scale, [head][token]
__device__ __align__(16) float  g_ksi[NKV * S_LEN];     // 1/scale,     [kvh][token]
__device__ __align__(16) __half g_vh[S_LEN * DKV];      // V in fp16

// fp16 hi/lo split buffers
__device__ __align__(16) __half g_xh[S_LEN * DMODEL],   g_xl[S_LEN * DMODEL];
__device__ __align__(16) __half g_wh[3072 * DMODEL],    g_wl[3072 * DMODEL];
__device__ __align__(16) __half g_woh[DMODEL * DMODEL];
__device__ __align__(16) __half g_ah[S_LEN * DMODEL];

#define NEG_INF (__int_as_float(0xff800000))

// =====================================================================
// helpers
// =====================================================================
__device__ __forceinline__ void mma_f16(float* c, const uint32_t* a,
                                        uint32_t b0, uint32_t b1) {
    asm("mma.sync.aligned.m16n8k16.row.col.f32.f16.f16.f32 "
        "{%0,%1,%2,%3}, {%4,%5,%6,%7}, {%8,%9}, {%0,%1,%2,%3};"
        : "+f"(c[0]), "+f"(c[1]), "+f"(c[2]), "+f"(c[3])
        : "r"(a[0]), "r"(a[1]), "r"(a[2]), "r"(a[3]), "r"(b0), "r"(b1));
}

__device__ __forceinline__ void mma_f16s(float* c, uint32_t a0, uint32_t a1,
                                         uint32_t a2, uint32_t a3,
                                         uint32_t b0, uint32_t b1) {
    asm("mma.sync.aligned.m16n8k16.row.col.f32.f16.f16.f32 "
        "{%0,%1,%2,%3}, {%4,%5,%6,%7}, {%8,%9}, {%0,%1,%2,%3};"
        : "+f"(c[0]), "+f"(c[1]), "+f"(c[2]), "+f"(c[3])
        : "r"(a0), "r"(a1), "r"(a2), "r"(a3), "r"(b0), "r"(b1));
}

__device__ __forceinline__ void mma_s8(int* c, const int* a, int b0, int b1) {
    asm("mma.sync.aligned.m16n8k32.row.col.s32.s8.s8.s32 "
        "{%0,%1,%2,%3}, {%4,%5,%6,%7}, {%8,%9}, {%0,%1,%2,%3};"
        : "+r"(c[0]), "+r"(c[1]), "+r"(c[2]), "+r"(c[3])
        : "r"(a[0]), "r"(a[1]), "r"(a[2]), "r"(a[3]), "r"(b0), "r"(b1));
}

#define LDSM4(r, a) \
    asm volatile("ldmatrix.sync.aligned.m8n8.x4.shared.b16 {%0,%1,%2,%3}, [%4];" \
                 : "=r"((r)[0]), "=r"((r)[1]), "=r"((r)[2]), "=r"((r)[3]) : "r"(a))

#define LDSM2T(r0, r1, a) \
    asm volatile("ldmatrix.sync.aligned.m8n8.x2.trans.shared.b16 {%0,%1}, [%2];" \
                 : "=r"(r0), "=r"(r1) : "r"(a))

#define CP_ASYNC16(dst, src) \
    asm volatile("cp.async.ca.shared.global [%0], [%1], 16;" :: "r"(dst), "l"(src))
#define CP_COMMIT() asm volatile("cp.async.commit_group;")
#define CP_WAIT(n)  asm volatile("cp.async.wait_group %0;" :: "n"(n))

__device__ __forceinline__ uint32_t smem_u32(const void* p) {
    uint32_t a;
    asm("{ .reg .u64 t; cvta.to.shared.u64 t, %1; cvt.u32.u64 %0, t; }" : "=r"(a) : "l"(p));
    return a;
}

// =====================================================================
// Prep: split fp32 inputs into fp16 hi/lo pairs (Wo: hi only)
// =====================================================================
__device__ __forceinline__ void split4(float4 v, __half* dh, __half* dl, size_t e) {
    __half h0 = __float2half_rn(v.x), h1 = __float2half_rn(v.y);
    __half h2 = __float2half_rn(v.z), h3 = __float2half_rn(v.w);
    __half2 a, b;
    a.x = h0; a.y = h1; b.x = h2; b.y = h3;
    *reinterpret_cast<__half2*>(dh + e)     = a;
    *reinterpret_cast<__half2*>(dh + e + 2) = b;
    __half2 c, d;
    c.x = __float2half_rn(v.x - __half2float(h0));
    c.y = __float2half_rn(v.y - __half2float(h1));
    d.x = __float2half_rn(v.z - __half2float(h2));
    d.y = __float2half_rn(v.w - __half2float(h3));
    *reinterpret_cast<__half2*>(dl + e)     = c;
    *reinterpret_cast<__half2*>(dl + e + 2) = d;
}

__global__ __launch_bounds__(256) void prep_kernel(
    const float* __restrict__ x, const float* __restrict__ Wq,
    const float* __restrict__ Wk, const float* __restrict__ Wv,
    const float* __restrict__ Wo)
{
    const int NX = S_LEN * DMODEL / 4;
    const int NW = 3072 * DMODEL / 4;
    const int NO = DMODEL * DMODEL / 4;
    const int total = NX + NW + NO;
    for (int i = blockIdx.x * blockDim.x + threadIdx.x; i < total;
         i += gridDim.x * blockDim.x) {
        if (i < NX) {
            float4 v = reinterpret_cast<const float4*>(x)[i];
            split4(v, g_xh, g_xl, (size_t)i * 4);
        } else if (i < NX + NW) {
            int j = i - NX;
            int row = j >> 9;
            int c4  = j & 511;
            float4 v;
            if (row < 2048)      v = reinterpret_cast<const float4*>(Wq)[row * 512 + c4];
            else if (row < 2560) v = reinterpret_cast<const float4*>(Wk)[(row - 2048) * 512 + c4];
            else                 v = reinterpret_cast<const float4*>(Wv)[(row - 2560) * 512 + c4];
            split4(v, g_wh, g_wl, (size_t)j * 4);
        } else {
            int j = i - NX - NW;
            float4 v = reinterpret_cast<const float4*>(Wo)[j];
            *reinterpret_cast<__half2*>(g_woh + (size_t)j * 4)     = __floats2half2_rn(v.x, v.y);
            *reinterpret_cast<__half2*>(g_woh + (size_t)j * 4 + 2) = __floats2half2_rn(v.z, v.w);
        }
    }
}

// =====================================================================
// QKV GEMM: fp16 hi/lo, Q/K 3-term + quant, V 2-term -> fp16 g_vh.
// 4-stage cp.async pipeline, 128x128 CTA, 2 CTA/SM.
// =====================================================================
#define GP       48
#define TILE_B   6144
#define STAGE_B  24576
#define NSTAGE   4
#define SMEM_DYN (NSTAGE * STAGE_B)   // 98304
#define KITER    128

__global__ __launch_bounds__(256, 2) void qkv_gemm()
{
    extern __shared__ char smem[];
    const uint32_t sbase = smem_u32(smem);
    const int tid  = threadIdx.x;
    const int wid  = tid >> 5;
    const int lane = tid & 31;
    const int m0   = blockIdx.x * 128;
    const int n0   = blockIdx.y * 128;     // V tiles (n0 >= 2560) launch last
    const int wm   = (wid & 3) * 32;
    const int wn   = (wid >> 2) * 64;

    const int mode = (n0 < 2048) ? 0 : (n0 < 2560) ? 1 : 2;   // 0=Q 1=K 2=V
    const int nterms = (mode <= 1) ? 3 : 2;
    const __half* srcs[4] = {
        g_xh + (size_t)m0 * DMODEL, g_xl + (size_t)m0 * DMODEL,
        g_wh + (size_t)n0 * DMODEL, g_wl + (size_t)n0 * DMODEL };

    const int r0 = tid >> 1;
    const int s0 = tid & 1;

    const uint32_t aAddr = sbase + (wm + (lane & 15)) * GP + ((lane >> 4) << 4);
    const uint32_t bAddr = sbase + 2 * TILE_B +
        (wn + (lane & 7) + ((lane >> 4) & 1) * 8) * GP + (((lane >> 3) & 1) << 4);

    float acc[2][8][4];
#pragma unroll
    for (int mt = 0; mt < 2; mt++)
#pragma unroll
        for (int nt = 0; nt < 8; nt++)
#pragma unroll
            for (int i = 0; i < 4; i++) acc[mt][nt][i] = 0.f;

    auto load_stage = [&](int it) {
        const int kc = it * 16;
        const uint32_t db = sbase + (it & (NSTAGE - 1)) * STAGE_B;
        const uint32_t d0 = db + r0 * GP + s0 * 16;
        const size_t   so = (size_t)r0 * DMODEL + kc + s0 * 8;
        CP_ASYNC16(d0,              (const char*)(srcs[0] + so));
        CP_ASYNC16(d0 + 2 * TILE_B, (const char*)(srcs[2] + so));
        CP_ASYNC16(d0 + TILE_B,     (const char*)(srcs[1] + so));
        if (nterms == 3)
            CP_ASYNC16(d0 + 3 * TILE_B, (const char*)(srcs[3] + so));
    };

    load_stage(0); CP_COMMIT();
    load_stage(1); CP_COMMIT();
    load_stage(2); CP_COMMIT();

    for (int it = 0; it < KITER; it++) {
        CP_WAIT(2);
        __syncthreads();
        if (it + 3 < KITER) load_stage(it + 3);
        CP_COMMIT();

        const uint32_t off = (it & (NSTAGE - 1)) * STAGE_B;
        const uint32_t ab = aAddr + off;
        const uint32_t bb = bAddr + off;
        uint32_t ah[2][4], al[2][4], bh[4][4];
#pragma unroll
        for (int mt = 0; mt < 2; mt++) {
            LDSM4(ah[mt], ab + mt * (16 * GP));
            LDSM4(al[mt], ab + mt * (16 * GP) + TILE_B);
        }
#pragma unroll
        for (int np = 0; np < 4; np++)
            LDSM4(bh[np], bb + np * (16 * GP));

#pragma unroll
        for (int mt = 0; mt < 2; mt++)
#pragma unroll
            for (int nt = 0; nt < 8; nt++)
                mma_f16(acc[mt][nt], ah[mt],
                        bh[nt >> 1][(nt & 1) * 2], bh[nt >> 1][(nt & 1) * 2 + 1]);
#pragma unroll
        for (int mt = 0; mt < 2; mt++)
#pragma unroll
            for (int nt = 0; nt < 8; nt++)
                mma_f16(acc[mt][nt], al[mt],
                        bh[nt >> 1][(nt & 1) * 2], bh[nt >> 1][(nt & 1) * 2 + 1]);
        if (nterms == 3) {
            uint32_t bl[4][4];
#pragma unroll
            for (int np = 0; np < 4; np++)
                LDSM4(bl[np], bb + np * (16 * GP) + TILE_B);
#pragma unroll
            for (int mt = 0; mt < 2; mt++)
#pragma unroll
                for (int nt = 0; nt < 8; nt++)
                    mma_f16(acc[mt][nt], ah[mt],
                            bl[nt >> 1][(nt & 1) * 2], bl[nt >> 1][(nt & 1) * 2 + 1]);
        }
    }

    // ---- epilogue ----
    const int qrow = lane >> 2;
    const int qcol = (lane & 3) * 2;
#pragma unroll
    for (int mt = 0; mt < 2; mt++) {
#pragma unroll
        for (int h = 0; h < 2; h++) {
            const int row = m0 + wm + mt * 16 + qrow + h * 8;
            if (mode <= 1) {
                float am = 0.f;
#pragma unroll
                for (int nt = 0; nt < 8; nt++)
                    am = fmaxf(am, fmaxf(fabsf(acc[mt][nt][h * 2]),
                                         fabsf(acc[mt][nt][h * 2 + 1])));
                am = fmaxf(am, __shfl_xor_sync(0xffffffffu, am, 1));
                am = fmaxf(am, __shfl_xor_sync(0xffffffffu, am, 2));
                float scale = 127.f / fmaxf(am, 1e-6f);
#pragma unroll
                for (int nt = 0; nt < 8; nt++) {
                    int v0 = min(127, max(-127, __float2int_rn(acc[mt][nt][h * 2]     * scale)));
                    int v1 = min(127, max(-127, __float2int_rn(acc[mt][nt][h * 2 + 1] * scale)));
                    unsigned short pk = (unsigned short)((v0 & 255) | ((v1 & 255) << 8));
                    if (mode == 0)
                        *reinterpret_cast<unsigned short*>(
                            &g_q8[(size_t)row * DMODEL + n0 + wn + nt * 8 + qcol]) = pk;
                    else
                        *reinterpret_cast<unsigned short*>(
                            &g_k8[(size_t)row * DKV + (n0 - 2048) + wn + nt * 8 + qcol]) = pk;
                }
                if ((lane & 3) == 0) {
                    if (mode == 0)
                        g_qsi[(size_t)((n0 + wn) >> 6) * S_LEN + row] = 0.125f / scale;
                    else
                        g_ksi[(size_t)(((n0 - 2048) + wn) >> 6) * S_LEN + row] = 1.f / scale;
                }
            } else {
#pragma unroll
                for (int nt = 0; nt < 8; nt++) {
                    __half2 hv = __floats2half2_rn(acc[mt][nt][h * 2], acc[mt][nt][h * 2 + 1]);
                    *reinterpret_cast<__half2*>(
                        &g_vh[(size_t)row * DKV + (n0 - 2560) + wn + nt * 8 + qcol]) = hv;
                }
            }
        }
    }
}

// =====================================================================
// Out GEMM: 1-term fp16, CTA 128x256 (8 warps of 64x64), BK=16,
// 4-stage cp.async pipeline, single wave (128 CTAs).
// =====================================================================
#define WA_TILE   6144          // A: 128 * 48
#define WB_TILE   12288         // B: 256 * 48
#define WSTAGE_B  18432
#define WSMEM_DYN (NSTAGE * WSTAGE_B)   // 73728

__global__ __launch_bounds__(256, 1) void out_gemm(float* __restrict__ outp)
{
    extern __shared__ char smem[];
    const uint32_t sbase = smem_u32(smem);
    const int tid  = threadIdx.x;
    const int wid  = tid >> 5;
    const int lane = tid & 31;
    const int m0   = blockIdx.x * 128;
    const int n0   = blockIdx.y * 256;
    const int wm   = (wid & 1) * 64;
    const int wn   = (wid >> 1) * 64;

    const __half* Asrc = g_ah  + (size_t)m0 * DMODEL;
    const __half* Bsrc = g_woh + (size_t)n0 * DMODEL;

    const int r0 = tid >> 1;
    const int sb = (tid & 1) * 16;
    const size_t go = (size_t)r0 * DMODEL + (tid & 1) * 8;

    const uint32_t aAddr = sbase + (wm + (lane & 15)) * GP + ((lane >> 4) << 4);
    const uint32_t bAddr = sbase + WA_TILE +
        (wn + (lane & 7) + ((lane >> 4) & 1) * 8) * GP + (((lane >> 3) & 1) << 4);

    float acc[4][8][4];
#pragma unroll
    for (int mt = 0; mt < 4; mt++)
#pragma unroll
        for (int nt = 0; nt < 8; nt++)
#pragma unroll
            for (int i = 0; i < 4; i++) acc[mt][nt][i] = 0.f;

    auto load_stage = [&](int it) {
        const int kc = it * 16;
        const uint32_t db = sbase + (it & (NSTAGE - 1)) * WSTAGE_B + r0 * GP + sb;
        CP_ASYNC16(db,                       (const char*)(Asrc + go + kc));
        CP_ASYNC16(db + WA_TILE,             (const char*)(Bsrc + go + kc));
        CP_ASYNC16(db + WA_TILE + 128 * GP,
                   (const char*)(Bsrc + go + (size_t)128 * DMODEL + kc));
    };

    load_stage(0); CP_COMMIT();
    load_stage(1); CP_COMMIT();
    load_stage(2); CP_COMMIT();

    for (int it = 0; it < KITER; it++) {
        CP_WAIT(2);
        __syncthreads();
        if (it + 3 < KITER) load_stage(it + 3);
        CP_COMMIT();

        const uint32_t off = (it & (NSTAGE - 1)) * WSTAGE_B;
        const uint32_t ab = aAddr + off;
        const uint32_t bb = bAddr + off;
        uint32_t ah[4][4], bh[4][4];
#pragma unroll
        for (int q = 0; q < 4; q++)
            LDSM4(ah[q], ab + q * (16 * GP));
#pragma unroll
        for (int np = 0; np < 4; np++)
            LDSM4(bh[np], bb + np * (16 * GP));
#pragma unroll
        for (int mt = 0; mt < 4; mt++)
#pragma unroll
            for (int nt = 0; nt < 8; nt++)
                mma_f16(acc[mt][nt], ah[mt],
                        bh[nt >> 1][(nt & 1) * 2], bh[nt >> 1][(nt & 1) * 2 + 1]);
    }

    const int qrow = lane >> 2;
    const int qcol = (lane & 3) * 2;
#pragma unroll
    for (int mt = 0; mt < 4; mt++)
#pragma unroll
        for (int h = 0; h < 2; h++) {
            const int row = m0 + wm + mt * 16 + qrow + h * 8;
#pragma unroll
            for (int nt = 0; nt < 8; nt++) {
                float2 v = make_float2(acc[mt][nt][h * 2], acc[mt][nt][h * 2 + 1]);
                *reinterpret_cast<float2*>(
                    &outp[(size_t)row * DMODEL + n0 + wn + nt * 8 + qcol]) = v;
            }
        }
}

// =====================================================================
// Attention: s8 scores + fp16 PV; K/V/scales double-buffered via cp.async
// =====================================================================
__global__ __launch_bounds__(128) void attn_kernel()
{
    const int h    = blockIdx.y;
    const int qb   = gridDim.x - 1 - blockIdx.x;
    const int kvh  = h >> 2;
    const int tid  = threadIdx.x;
    const int warp = tid >> 5;
    const int lane = tid & 31;
    const int g    = lane >> 2;
    const int tg   = lane & 3;
    const int rbase = warp * 16;

    __shared__ __align__(16) int    qsm[64][20];
    __shared__ __align__(16) int    ksm[2][64][20];     // pitch 80B
    __shared__ __align__(16) __half vsm[2][64][72];     // pitch 144B
    __shared__ __align__(16) __half psm[64][72];
    __shared__ __align__(16) float  kinvs[2][64];
    __shared__ float qfac[64];

    const uint32_t ks_base = smem_u32(&ksm[0][0][0]);
    const uint32_t vs_base = smem_u32(&vsm[0][0][0]);
    const uint32_t ki_base = smem_u32(&kinvs[0][0]);

    // ---- load Q tile + Q factors (once) ----
#pragma unroll
    for (int i = 0; i < 2; i++) {
        int idx = tid + i * 128;
        int row = idx >> 2;
        int seg = idx & 3;
        int4 v = *reinterpret_cast<const int4*>(
            &g_q8[(size_t)(qb * 64 + row) * DMODEL + h * 64 + seg * 16]);
        *reinterpret_cast<int4*>(&qsm[row][seg * 4]) = v;
    }
    if (tid < 64) qfac[tid] = g_qsi[(size_t)h * S_LEN + qb * 64 + tid];

    // ---- cp.async loader for K/V/scales of block j into buffer buf ----
    auto load_kv = [&](int j, int buf) {
        const uint32_t kb = ks_base + buf * 5120;
#pragma unroll
        for (int i = 0; i < 2; i++) {
            int idx = tid + i * 128;
            int row = idx >> 2, seg = idx & 3;
            CP_ASYNC16(kb + row * 80 + seg * 16,
                       (const char*)(g_k8 + (size_t)(j * 64 + row) * DKV + kvh * 64) + seg * 16);
        }
        const uint32_t vb = vs_base + buf * 9216;
#pragma unroll
        for (int i = 0; i < 4; i++) {
            int idx = tid + i * 128;
            int row = idx >> 3, seg = idx & 7;
            CP_ASYNC16(vb + row * 144 + seg * 16,
                       (const char*)(g_vh + (size_t)(j * 64 + row) * DKV + kvh * 64) + seg * 16);
        }
        if (tid < 16)
            CP_ASYNC16(ki_base + buf * 256 + tid * 16,
                       (const char*)(g_ksi + (size_t)kvh * S_LEN + j * 64) + tid * 16);
    };

    int qa[2][4];
    // Q fragments need qsm ready
    __syncthreads();
#pragma unroll
    for (int s = 0; s < 2; s++) {
        qa[s][0] = qsm[rbase + g    ][s * 8 + tg];
        qa[s][1] = qsm[rbase + g + 8][s * 8 + tg];
        qa[s][2] = qsm[rbase + g    ][s * 8 + 4 + tg];
        qa[s][3] = qsm[rbase + g + 8][s * 8 + 4 + tg];
    }

    const int   rowA = rbase + g, rowB = rowA + 8;
    const float qfA  = qfac[rowA], qfB = qfac[rowB];
    const int   qgA  = qb * 64 + rowA, qgB = qb * 64 + rowB;

    float acc[8][4];
#pragma unroll
    for (int nt = 0; nt < 8; nt++)
#pragma unroll
        for (int i = 0; i < 4; i++) acc[nt][i] = 0.f;
    float m_runA = NEG_INF, m_runB = NEG_INF;
    float l_runA = 0.f,     l_runB = 0.f;

    load_kv(0, 0); CP_COMMIT();

    for (int j = 0; j <= qb; j++) {
        const int buf = j & 1;
        if (j < qb) load_kv(j + 1, buf ^ 1);
        CP_COMMIT();
        CP_WAIT(1);
        __syncthreads();   // block-j data visible to all threads

        const uint32_t vbase = vs_base + buf * 9216 + (lane & 15) * 144;

        int sc[8][4];
#pragma unroll
        for (int nt = 0; nt < 8; nt++) {
            sc[nt][0] = sc[nt][1] = sc[nt][2] = sc[nt][3] = 0;
#pragma unroll
            for (int s = 0; s < 2; s++) {
                int b0 = ksm[buf][nt * 8 + g][s * 8 + tg];
                int b1 = ksm[buf][nt * 8 + g][s * 8 + 4 + tg];
                mma_s8(sc[nt], qa[s], b0, b1);
            }
        }

        const bool maskblk = (j == qb);
        float sv[8][4];
        float mxA = NEG_INF, mxB = NEG_INF;
#pragma unroll
        for (int nt = 0; nt < 8; nt++) {
            int colbase = nt * 8 + tg * 2;
            float2 kv = *reinterpret_cast<const float2*>(&kinvs[buf][colbase]);
            float s0 = (float)sc[nt][0] * qfA * kv.x;
            float s1 = (float)sc[nt][1] * qfA * kv.y;
            float s2 = (float)sc[nt][2] * qfB * kv.x;
            float s3 = (float)sc[nt][3] * qfB * kv.y;
            if (maskblk) {
                int col = j * 64 + colbase;
                if (col     > qgA) s0 = NEG_INF;
                if (col + 1 > qgA) s1 = NEG_INF;
                if (col     > qgB) s2 = NEG_INF;
                if (col + 1 > qgB) s3 = NEG_INF;
            }
            sv[nt][0] = s0; sv[nt][1] = s1; sv[nt][2] = s2; sv[nt][3] = s3;
            mxA = fmaxf(mxA, fmaxf(s0, s1));
            mxB = fmaxf(mxB, fmaxf(s2, s3));
        }
        mxA = fmaxf(mxA, __shfl_xor_sync(0xffffffffu, mxA, 1));
        mxA = fmaxf(mxA, __shfl_xor_sync(0xffffffffu, mxA, 2));
        mxB = fmaxf(mxB, __shfl_xor_sync(0xffffffffu, mxB, 1));
        mxB = fmaxf(mxB, __shfl_xor_sync(0xffffffffu, mxB, 2));

        float mA = fmaxf(m_runA, mxA);
        float mB = fmaxf(m_runB, mxB);
        float aA = __expf(m_runA - mA);
        float aB = __expf(m_runB - mB);
        m_runA = mA; m_runB = mB;

        float sumA = 0.f, sumB = 0.f;
#pragma unroll
        for (int nt = 0; nt < 8; nt++) {
            int colbase = nt * 8 + tg * 2;
            float p0 = __expf(sv[nt][0] - mA);
            float p1 = __expf(sv[nt][1] - mA);
            float p2 = __expf(sv[nt][2] - mB);
            float p3 = __expf(sv[nt][3] - mB);
            sumA += p0 + p1; sumB += p2 + p3;
            *reinterpret_cast<__half2*>(&psm[rowA][colbase]) = __floats2half2_rn(p0, p1);
            *reinterpret_cast<__half2*>(&psm[rowB][colbase]) = __floats2half2_rn(p2, p3);
        }
        sumA += __shfl_xor_sync(0xffffffffu, sumA, 1);
        sumA += __shfl_xor_sync(0xffffffffu, sumA, 2);
        sumB += __shfl_xor_sync(0xffffffffu, sumB, 1);
        sumB += __shfl_xor_sync(0xffffffffu, sumB, 2);
        l_runA = l_runA * aA + sumA;
        l_runB = l_runB * aB + sumB;

#pragma unroll
        for (int nt = 0; nt < 8; nt++) {
            acc[nt][0] *= aA; acc[nt][1] *= aA;
            acc[nt][2] *= aB; acc[nt][3] *= aB;
        }

        __syncwarp();   // psm rows are warp-private

#pragma unroll
        for (int ks = 0; ks < 4; ks++) {
            uint32_t a0 = *reinterpret_cast<const uint32_t*>(&psm[rowA][ks * 16 + tg * 2]);
            uint32_t a1 = *reinterpret_cast<const uint32_t*>(&psm[rowB][ks * 16 + tg * 2]);
            uint32_t a2 = *reinterpret_cast<const uint32_t*>(&psm[rowA][ks * 16 + 8 + tg * 2]);
            uint32_t a3 = *reinterpret_cast<const uint32_t*>(&psm[rowB][ks * 16 + 8 + tg * 2]);
            const uint32_t vrow = vbase + ks * (16 * 144);
#pragma unroll
            for (int nt = 0; nt < 8; nt++) {
                uint32_t b0, b1;
                LDSM2T(b0, b1, vrow + nt * 16);
                mma_f16s(acc[nt], a0, a1, a2, a3, b0, b1);
            }
        }

        __syncthreads();   // all reads of buf done before next iter overwrites buf^1's successor
    }

    // ---- epilogue: fp16 hi for the 1-term out-projection ----
    float ilA = 1.f / l_runA, ilB = 1.f / l_runB;
#pragma unroll
    for (int nt = 0; nt < 8; nt++) {
        int colbase = nt * 8 + tg * 2;
        float oA0 = acc[nt][0] * ilA, oA1 = acc[nt][1] * ilA;
        float oB0 = acc[nt][2] * ilB, oB1 = acc[nt][3] * ilB;
        size_t pA = (size_t)qgA * DMODEL + h * 64 + colbase;
        size_t pB = (size_t)qgB * DMODEL + h * 64 + colbase;
        *reinterpret_cast<__half2*>(&g_ah[pA]) = __floats2half2_rn(oA0, oA1);
        *reinterpret_cast<__half2*>(&g_ah[pB]) = __floats2half2_rn(oB0, oB1);
    }
}

// =====================================================================
extern "C" void kernel_launch(void* const* d_in, const int* in_sizes, int n_in,
                              void* d_out, int out_size)
{
    const float* x  = (const float*)d_in[0];
    const float* Wq = (const float*)d_in[1];
    const float* Wk = (const float*)d_in[2];
    const float* Wv = (const float*)d_in[3];
    const float* Wo = (const float*)d_in[4];
    float* out = (float*)d_out;

    cudaFuncSetAttribute(qkv_gemm, cudaFuncAttributeMaxDynamicSharedMemorySize, SMEM_DYN);
    cudaFuncSetAttribute(out_gemm, cudaFuncAttributeMaxDynamicSharedMemorySize, WSMEM_DYN);

    prep_kernel<<<592, 256>>>(x, Wq, Wk, Wv, Wo);
    qkv_gemm<<<dim3(16, 24), 256, SMEM_DYN>>>();            // QKV (V tiles last)
    attn_kernel<<<dim3(32, 32), 128>>>();
    out_gemm<<<dim3(16, 8), 256, WSMEM_DYN>>>(out);         // 128x256 tiles, 1 wave
}